// round 1
// baseline (speedup 1.0000x reference)
#include <cuda_runtime.h>
#include <cuda_bf16.h>
#include <math.h>

// Problem constants
#define BATCH   2
#define SEQ     2048
#define HID     4096
#define NHEADS  32
#define NKV     8
#define NREP    4
#define HD      128
#define SCALING 0.08838834764831845f   // 128^-0.5
#define NEG_BIG (-1.0e30f)

// Scratch (device globals: allocation-free per harness rules)
__device__ float g_q[BATCH * NHEADS * SEQ * HD];     // [b,h,s,d]
__device__ float g_k[BATCH * NKV * SEQ * HD];        // [b,kv,s,d]
__device__ float g_v[BATCH * NKV * SEQ * HD];        // [b,kv,s,d]
__device__ float g_attn[BATCH * SEQ * NHEADS * HD];  // [b,s,h,d]

// ---------------------------------------------------------------------------
// GEMM: C = A[M,K] @ W[K,N].  BM=BN=128, BK=8, 256 threads, 8x8 per thread.
// MODE 0: C[m*N+n] plain row-major.
// MODE 1: QKV epilogue: m=(b,s), n=(h,d) -> C[((b*nh+h)*SEQ+s)*HD+d]
// ---------------------------------------------------------------------------
template <int MODE>
__global__ __launch_bounds__(256) void gemm_kernel(
    const float* __restrict__ A, const float* __restrict__ W,
    float* __restrict__ C, int M, int N, int K, int nh)
{
    __shared__ float sA[8][132];
    __shared__ float sB[8][132];

    const int tid = threadIdx.x;
    const int m0 = blockIdx.y * 128;
    const int n0 = blockIdx.x * 128;
    const int tx = tid & 15;
    const int ty = tid >> 4;

    float acc[8][8];
#pragma unroll
    for (int i = 0; i < 8; i++)
#pragma unroll
        for (int j = 0; j < 8; j++) acc[i][j] = 0.f;

    const int am = tid >> 1;            // row within A tile (0..127)
    const int ak = (tid & 1) * 4;       // k-subcolumn (0 or 4)
    const int bk = tid >> 5;            // row within W tile (0..7)
    const int bn = (tid & 31) * 4;      // col within W tile

    const float* Aptr = A + (size_t)(m0 + am) * K + ak;
    const float* Wptr = W + (size_t)bk * N + n0 + bn;

    for (int k0 = 0; k0 < K; k0 += 8) {
        float4 av = *(const float4*)(Aptr + k0);
        float4 bv = *(const float4*)(Wptr + (size_t)k0 * N);
        sA[ak + 0][am] = av.x;
        sA[ak + 1][am] = av.y;
        sA[ak + 2][am] = av.z;
        sA[ak + 3][am] = av.w;
        *(float4*)&sB[bk][bn] = bv;
        __syncthreads();

#pragma unroll
        for (int kk = 0; kk < 8; kk++) {
            float a[8], b[8];
            *(float4*)(a)     = *(const float4*)&sA[kk][ty * 8];
            *(float4*)(a + 4) = *(const float4*)&sA[kk][ty * 8 + 4];
            *(float4*)(b)     = *(const float4*)&sB[kk][tx * 8];
            *(float4*)(b + 4) = *(const float4*)&sB[kk][tx * 8 + 4];
#pragma unroll
            for (int i = 0; i < 8; i++)
#pragma unroll
                for (int j = 0; j < 8; j++) acc[i][j] = fmaf(a[i], b[j], acc[i][j]);
        }
        __syncthreads();
    }

#pragma unroll
    for (int i = 0; i < 8; i++) {
        const int m = m0 + ty * 8 + i;
#pragma unroll
        for (int j = 0; j < 8; j += 4) {
            const int n = n0 + tx * 8 + j;
            float4 o = make_float4(acc[i][j], acc[i][j + 1], acc[i][j + 2], acc[i][j + 3]);
            if (MODE == 0) {
                *(float4*)&C[(size_t)m * N + n] = o;
            } else {
                const int b = m >> 11;         // /SEQ
                const int s = m & (SEQ - 1);
                const int h = n >> 7;          // /HD
                const int d = n & (HD - 1);
                *(float4*)&C[((size_t)(b * nh + h) * SEQ + s) * HD + d] = o;
            }
        }
    }
}

// ---------------------------------------------------------------------------
// RoPE (in place) on [B, nh, S, HD]; pair (d, d+64)
// ---------------------------------------------------------------------------
__global__ void rope_kernel(float* __restrict__ x,
                            const float* __restrict__ cosb,
                            const float* __restrict__ sinb, int nh, int total)
{
    int idx = blockIdx.x * blockDim.x + threadIdx.x;
    if (idx >= total) return;
    const int d = idx & 63;
    const int row = idx >> 6;                 // over [b, nh, s]
    const int s = row & (SEQ - 1);
    const int b = (row / SEQ) / nh;
    float* xr = x + (size_t)row * HD;
    const float* cb = cosb + ((size_t)b * SEQ + s) * HD;
    const float* sb = sinb + ((size_t)b * SEQ + s) * HD;
    const float x0 = xr[d];
    const float x1 = xr[d + 64];
    xr[d]      = x0 * cb[d]      - x1 * sb[d];
    xr[d + 64] = x1 * cb[d + 64] + x0 * sb[d + 64];
}

// ---------------------------------------------------------------------------
// Flash attention, fp32. TQ=TK=64, 256 threads per block.
// Block = (b, h, q-tile). Causal via k-tile bound + last-tile mask.
// Output to g_attn [b, s, h, d].
// smem: sQt[128][68], sKt[128][68], sV[64][132], sS[64][68], sM/sL/sC[64]
// ---------------------------------------------------------------------------
#define FL_SMEM ((128 * 68 * 2 + 64 * 132 + 64 * 68 + 192) * 4)

__global__ __launch_bounds__(256) void flash_kernel(
    const float* __restrict__ Q, const float* __restrict__ K,
    const float* __restrict__ V, float* __restrict__ O)
{
    extern __shared__ float smem[];
    float* sQt = smem;                  // [128][68] (d-major, row index r)
    float* sKt = sQt + 128 * 68;        // [128][68] (d-major, col index c)
    float* sV  = sKt + 128 * 68;        // [64][132]
    float* sS  = sV + 64 * 132;         // [64][68]
    float* sM  = sS + 64 * 68;
    float* sL  = sM + 64;
    float* sC  = sL + 64;

    const int tid = threadIdx.x;
    const int nqt = SEQ / 64;           // 32
    const int bh = blockIdx.x / nqt;
    const int qt = blockIdx.x % nqt;
    const int b = bh / NHEADS;
    const int h = bh % NHEADS;
    const int kvh = h / NREP;
    const int q0 = qt * 64;

    const float* Qb = Q + (size_t)(b * NHEADS + h) * SEQ * HD;
    const float* Kb = K + (size_t)(b * NKV + kvh) * SEQ * HD;
    const float* Vb = V + (size_t)(b * NKV + kvh) * SEQ * HD;

    // Load Q tile transposed: sQt[d][r]
    for (int e = tid; e < 64 * HD / 4; e += 256) {
        const int r = e >> 5;
        const int d4 = (e & 31) * 4;
        float4 v = *(const float4*)&Qb[(size_t)(q0 + r) * HD + d4];
        sQt[(d4 + 0) * 68 + r] = v.x;
        sQt[(d4 + 1) * 68 + r] = v.y;
        sQt[(d4 + 2) * 68 + r] = v.z;
        sQt[(d4 + 3) * 68 + r] = v.w;
    }
    if (tid < 64) { sM[tid] = -INFINITY; sL[tid] = 0.f; }

    float acc[4][8];
#pragma unroll
    for (int j = 0; j < 4; j++)
#pragma unroll
        for (int i = 0; i < 8; i++) acc[j][i] = 0.f;

    const int rg = tid >> 4;    // 0..15 (PV/QK row group: rows rg*4..+3)
    const int cg = tid & 15;    // PV col group: d = cg*8..+7 ; QK cols cg*4..+3
    const int r4 = tid >> 2;    // softmax: row
    const int t4 = tid & 3;     // softmax: quarter

    const int nkt = qt + 1;
    for (int kt = 0; kt < nkt; kt++) {
        const int k0 = kt * 64;
        __syncthreads();  // previous iter done with sKt/sV/sS
        for (int e = tid; e < 64 * HD / 4; e += 256) {
            const int r = e >> 5;
            const int d4 = (e & 31) * 4;
            float4 kv = *(const float4*)&Kb[(size_t)(k0 + r) * HD + d4];
            sKt[(d4 + 0) * 68 + r] = kv.x;
            sKt[(d4 + 1) * 68 + r] = kv.y;
            sKt[(d4 + 2) * 68 + r] = kv.z;
            sKt[(d4 + 3) * 68 + r] = kv.w;
            float4 vv = *(const float4*)&Vb[(size_t)(k0 + r) * HD + d4];
            *(float4*)&sV[r * 132 + d4] = vv;
        }
        __syncthreads();

        // ---- QK^T : 4x4 microtile per thread ----
        const int rq = rg * 4;
        const int cq = cg * 4;
        float sc[4][4];
#pragma unroll
        for (int j = 0; j < 4; j++)
#pragma unroll
            for (int i = 0; i < 4; i++) sc[j][i] = 0.f;
#pragma unroll 8
        for (int kk = 0; kk < HD; kk++) {
            float a[4], bb[4];
            *(float4*)a  = *(const float4*)&sQt[kk * 68 + rq];
            *(float4*)bb = *(const float4*)&sKt[kk * 68 + cq];
#pragma unroll
            for (int j = 0; j < 4; j++)
#pragma unroll
                for (int i = 0; i < 4; i++) sc[j][i] = fmaf(a[j], bb[i], sc[j][i]);
        }
#pragma unroll
        for (int j = 0; j < 4; j++)
#pragma unroll
            for (int i = 0; i < 4; i++) {
                float val = sc[j][i] * SCALING;
                if (k0 + cq + i > q0 + rq + j) val = NEG_BIG;
                sS[(rq + j) * 68 + cq + i] = val;
            }
        __syncthreads();

        // ---- online softmax: 4 threads per row ----
        {
            float lm = -INFINITY;
            const int cbase = t4 * 16;
#pragma unroll
            for (int c = 0; c < 16; c++) lm = fmaxf(lm, sS[r4 * 68 + cbase + c]);
            lm = fmaxf(lm, __shfl_xor_sync(0xffffffffu, lm, 1));
            lm = fmaxf(lm, __shfl_xor_sync(0xffffffffu, lm, 2));
            const float mold = sM[r4];
            const float mnew = fmaxf(mold, lm);
            float lsum = 0.f;
#pragma unroll
            for (int c = 0; c < 16; c++) {
                float p = __expf(sS[r4 * 68 + cbase + c] - mnew);
                sS[r4 * 68 + cbase + c] = p;
                lsum += p;
            }
            lsum += __shfl_xor_sync(0xffffffffu, lsum, 1);
            lsum += __shfl_xor_sync(0xffffffffu, lsum, 2);
            if (t4 == 0) {
                const float corr = __expf(mold - mnew);
                sC[r4] = corr;
                sL[r4] = sL[r4] * corr + lsum;
                sM[r4] = mnew;
            }
        }
        __syncthreads();

        // ---- P @ V : 4x8 microtile (rows rg*4..+3, cols cg*8..+7) ----
#pragma unroll
        for (int j = 0; j < 4; j++) {
            const float corr = sC[rg * 4 + j];
#pragma unroll
            for (int i = 0; i < 8; i++) acc[j][i] *= corr;
        }
        for (int c = 0; c < 64; c += 4) {
            float p[4][4];
#pragma unroll
            for (int j = 0; j < 4; j++) {
                *(float4*)p[j] = *(const float4*)&sS[(rg * 4 + j) * 68 + c];
            }
#pragma unroll
            for (int cc = 0; cc < 4; cc++) {
                float v8[8];
                *(float4*)(v8)     = *(const float4*)&sV[(c + cc) * 132 + cg * 8];
                *(float4*)(v8 + 4) = *(const float4*)&sV[(c + cc) * 132 + cg * 8 + 4];
#pragma unroll
                for (int j = 0; j < 4; j++)
#pragma unroll
                    for (int i = 0; i < 8; i++)
                        acc[j][i] = fmaf(p[j][cc], v8[i], acc[j][i]);
            }
        }
    }

    // ---- epilogue: normalize + store to [b, s, h, d] ----
#pragma unroll
    for (int j = 0; j < 4; j++) {
        const int r = rg * 4 + j;
        const float inv = 1.f / sL[r];
        float* op = O + ((size_t)(b * SEQ + q0 + r) * NHEADS + h) * HD + cg * 8;
        float4 o0 = make_float4(acc[j][0] * inv, acc[j][1] * inv, acc[j][2] * inv, acc[j][3] * inv);
        float4 o1 = make_float4(acc[j][4] * inv, acc[j][5] * inv, acc[j][6] * inv, acc[j][7] * inv);
        *(float4*)(op)     = o0;
        *(float4*)(op + 4) = o1;
    }
}

// ---------------------------------------------------------------------------
extern "C" void kernel_launch(void* const* d_in, const int* in_sizes, int n_in,
                              void* d_out, int out_size)
{
    const float* X    = (const float*)d_in[0];  // hidden_states [B,S,HID]
    const float* cosb = (const float*)d_in[1];  // [B,S,HD]
    const float* sinb = (const float*)d_in[2];  // [B,S,HD]
    // d_in[3] = attention_mask (causal; handled analytically)
    const float* wq = (const float*)d_in[4];    // [HID, NHEADS*HD]
    const float* wk = (const float*)d_in[5];    // [HID, NKV*HD]
    const float* wv = (const float*)d_in[6];    // [HID, NKV*HD]
    const float* wo = (const float*)d_in[7];    // [NHEADS*HD, HID]
    float* out = (float*)d_out;

    void *pq, *pk, *pv, *pa;
    cudaGetSymbolAddress(&pq, g_q);
    cudaGetSymbolAddress(&pk, g_k);
    cudaGetSymbolAddress(&pv, g_v);
    cudaGetSymbolAddress(&pa, g_attn);
    float* Qb = (float*)pq;
    float* Kb = (float*)pk;
    float* Vb = (float*)pv;
    float* Ab = (float*)pa;

    static bool attr_set = false;
    if (!attr_set) {
        cudaFuncSetAttribute(flash_kernel, cudaFuncAttributeMaxDynamicSharedMemorySize, FL_SMEM);
        attr_set = true;
    }

    const int M = BATCH * SEQ;   // 4096

    // Projections (fused layout transform to [b,h,s,d])
    {
        dim3 gq(NHEADS * HD / 128, M / 128);
        gemm_kernel<1><<<gq, 256>>>(X, wq, Qb, M, NHEADS * HD, HID, NHEADS);
        dim3 gk(NKV * HD / 128, M / 128);
        gemm_kernel<1><<<gk, 256>>>(X, wk, Kb, M, NKV * HD, HID, NKV);
        gemm_kernel<1><<<gk, 256>>>(X, wv, Vb, M, NKV * HD, HID, NKV);
    }

    // RoPE on Q and K
    {
        int totq = BATCH * NHEADS * SEQ * 64;
        rope_kernel<<<(totq + 255) / 256, 256>>>(Qb, cosb, sinb, NHEADS, totq);
        int totk = BATCH * NKV * SEQ * 64;
        rope_kernel<<<(totk + 255) / 256, 256>>>(Kb, cosb, sinb, NKV, totk);
    }

    // Flash attention -> g_attn [b,s,h,d]
    {
        int nblocks = BATCH * NHEADS * (SEQ / 64);
        flash_kernel<<<nblocks, 256, FL_SMEM>>>(Qb, Kb, Vb, Ab);
    }

    // Output projection
    {
        dim3 go(HID / 128, M / 128);
        gemm_kernel<0><<<go, 256>>>(Ab, wo, out, M, HID, NHEADS * HD, 0);
    }
    (void)in_sizes; (void)n_in; (void)out_size;
}

// round 3
// speedup vs baseline: 1.9623x; 1.9623x over previous
#include <cuda_runtime.h>
#include <cuda_bf16.h>
#include <math.h>
#include <stdint.h>

// Problem constants
#define BATCH   2
#define SEQ     2048
#define HID     4096
#define NHEADS  32
#define NKV     8
#define NREP    4
#define HD      128
#define SCALING 0.08838834764831845f   // 128^-0.5
#define NEG_BIG (-1.0e30f)

// ---------------------------------------------------------------------------
// Scratch (device globals: allocation-free per harness rules)
// ---------------------------------------------------------------------------
__device__ float g_q[BATCH * NHEADS * SEQ * HD];     // [b,h,s,d]
__device__ float g_k[BATCH * NKV * SEQ * HD];        // [b,kv,s,d]
__device__ float g_v[BATCH * NKV * SEQ * HD];        // [b,kv,s,d]
__device__ float g_attn[BATCH * SEQ * NHEADS * HD];  // [b,s,h,d]

// bf16 split operands
__device__ __nv_bfloat16 g_xhi[4096 * 4096], g_xlo[4096 * 4096];
__device__ __nv_bfloat16 g_wqT_hi[4096 * 4096], g_wqT_lo[4096 * 4096];
__device__ __nv_bfloat16 g_wkT_hi[1024 * 4096], g_wkT_lo[1024 * 4096];
__device__ __nv_bfloat16 g_wvT_hi[1024 * 4096], g_wvT_lo[1024 * 4096];
__device__ __nv_bfloat16 g_woT_hi[4096 * 4096], g_woT_lo[4096 * 4096];
__device__ __nv_bfloat16 g_ahi[4096 * 4096], g_alo[4096 * 4096];

// ---------------------------------------------------------------------------
// PTX helpers (portable sm_80-era ops only: ldmatrix / mma.sync / cp.async)
// ---------------------------------------------------------------------------
__device__ __forceinline__ uint32_t smem_u32(const void* p) {
    uint32_t a;
    asm("{ .reg .u64 t; cvta.to.shared.u64 t, %1; cvt.u32.u64 %0, t; }"
        : "=r"(a) : "l"(p));
    return a;
}

#define CP_ASYNC16(dst, src) \
    asm volatile("cp.async.cg.shared.global [%0], [%1], 16;" :: "r"(dst), "l"(src) : "memory")
#define CP_COMMIT() asm volatile("cp.async.commit_group;" ::: "memory")
#define CP_WAIT0()  asm volatile("cp.async.wait_group 0;" ::: "memory")
#define CP_WAIT2()  asm volatile("cp.async.wait_group 2;" ::: "memory")

__device__ __forceinline__ void ldsm4(uint32_t* r, uint32_t addr) {
    asm volatile("ldmatrix.sync.aligned.m8n8.x4.shared.b16 {%0,%1,%2,%3}, [%4];"
        : "=r"(r[0]), "=r"(r[1]), "=r"(r[2]), "=r"(r[3]) : "r"(addr));
}

__device__ __forceinline__ void mma16816(float* d, const uint32_t* a, const uint32_t* b) {
    asm volatile(
        "mma.sync.aligned.m16n8k16.row.col.f32.bf16.bf16.f32 "
        "{%0,%1,%2,%3}, {%4,%5,%6,%7}, {%8,%9}, {%0,%1,%2,%3};"
        : "+f"(d[0]), "+f"(d[1]), "+f"(d[2]), "+f"(d[3])
        : "r"(a[0]), "r"(a[1]), "r"(a[2]), "r"(a[3]), "r"(b[0]), "r"(b[1]));
}

// SW64-style swizzle for 64-byte rows (keeps ldmatrix conflict-free)
__device__ __forceinline__ uint32_t sw64(uint32_t off) {
    return off ^ ((off >> 3) & 0x30);
}

// ---------------------------------------------------------------------------
// Split kernels: fp32 -> bf16 hi/lo
// ---------------------------------------------------------------------------
__global__ void split_kernel(const float* __restrict__ in,
                             __nv_bfloat16* __restrict__ hi,
                             __nv_bfloat16* __restrict__ lo, int n)
{
    int i = (blockIdx.x * blockDim.x + threadIdx.x) * 4;
    if (i >= n) return;
    float4 v = *(const float4*)(in + i);
    float a[4] = {v.x, v.y, v.z, v.w};
    unsigned short hs[4], ls[4];
#pragma unroll
    for (int j = 0; j < 4; j++) {
        __nv_bfloat16 h = __float2bfloat16(a[j]);
        __nv_bfloat16 l = __float2bfloat16(a[j] - __bfloat162float(h));
        hs[j] = *(unsigned short*)&h;
        ls[j] = *(unsigned short*)&l;
    }
    *(ushort4*)(hi + i) = make_ushort4(hs[0], hs[1], hs[2], hs[3]);
    *(ushort4*)(lo + i) = make_ushort4(ls[0], ls[1], ls[2], ls[3]);
}

// Transpose + split: in [K, N] row-major -> out [N, K] bf16 hi/lo
__global__ void splitT_kernel(const float* __restrict__ in,
                              __nv_bfloat16* __restrict__ hi,
                              __nv_bfloat16* __restrict__ lo, int K, int N)
{
    __shared__ float t[32][33];
    const int k0 = blockIdx.y * 32;
    const int n0 = blockIdx.x * 32;
    const int tx = threadIdx.x, ty = threadIdx.y;
    for (int i = ty; i < 32; i += 8)
        t[i][tx] = in[(size_t)(k0 + i) * N + n0 + tx];
    __syncthreads();
    for (int i = ty; i < 32; i += 8) {
        float a = t[tx][i];     // in[k0+tx][n0+i]
        __nv_bfloat16 h = __float2bfloat16(a);
        __nv_bfloat16 l = __float2bfloat16(a - __bfloat162float(h));
        size_t o = (size_t)(n0 + i) * K + k0 + tx;
        hi[o] = h;
        lo[o] = l;
    }
}

// ---------------------------------------------------------------------------
// mma.sync GEMM: C[M,N] = A[M,K] @ B^T, A/Bt bf16 hi/lo splits, fp32 accum.
// 128x128 tile / CTA, BK=32, 3-stage cp.async pipeline, 8 warps (2x4 M x N?
// -> warp = 32 rows x 64 cols).
// 3-pass split: AhiBhi + AhiBlo + AloBhi.
// MODE 0: C row-major.  MODE 1: scatter to [b,h,s,d].
// ---------------------------------------------------------------------------
#define GT_SMEM (3 * 32768)

template <int MODE>
__global__ __launch_bounds__(256, 1) void gemm_mma(
    const __nv_bfloat16* __restrict__ Ahi, const __nv_bfloat16* __restrict__ Alo,
    const __nv_bfloat16* __restrict__ Bhi, const __nv_bfloat16* __restrict__ Blo,
    float* __restrict__ C, int M, int N, int K, int nh)
{
    extern __shared__ char dsm[];
    const uint32_t sm_base = smem_u32(dsm);

    const int tid = threadIdx.x;
    const int wid = tid >> 5;
    const int lane = tid & 31;
    const int wm = wid & 3;          // 4 warp-rows * 32
    const int wn = wid >> 2;         // 2 warp-cols * 64
    const int m0 = blockIdx.y * 128;
    const int n0 = blockIdx.x * 128;

    const __nv_bfloat16* srcs[4] = {Ahi, Alo, Bhi, Blo};

    // stage: [Ahi 8KB][Alo 8KB][Bhi 8KB][Blo 8KB] ; rows of 64B (32 bf16)
    auto load_chunk = [&](int stage, int c) {
        const int k0 = c << 5;
        const uint32_t stb = sm_base + stage * 32768u;
#pragma unroll
        for (int it = 0; it < 8; it++) {
            int g = tid + it * 256;
            int arr = g >> 9;
            int ga = g & 511;
            int r = ga >> 2;
            int cg = ga & 3;
            int rowg = (arr < 2 ? m0 : n0) + r;
            const __nv_bfloat16* src = srcs[arr] + (size_t)rowg * K + k0 + cg * 8;
            uint32_t off = sw64((uint32_t)(r * 64 + cg * 16));
            CP_ASYNC16(stb + arr * 8192u + off, src);
        }
        CP_COMMIT();
    };

    float acc[2][8][4];
#pragma unroll
    for (int mt = 0; mt < 2; mt++)
#pragma unroll
        for (int nt = 0; nt < 8; nt++)
#pragma unroll
            for (int i = 0; i < 4; i++) acc[mt][nt][i] = 0.f;

    const int NC = K >> 5;
    load_chunk(0, 0);
    load_chunk(1, 1);

    // precomputed intra-warp ldmatrix offsets
    const uint32_t a_row = wm * 32 + (lane & 15);
    const uint32_t a_c16 = (lane >> 4);
    const uint32_t b_row = wn * 64 + ((lane >> 4) & 1) * 8 + (lane & 7);
    const uint32_t b_c16 = (lane >> 3) & 1;

    for (int c = 0; c < NC; c++) {
        if (c + 2 < NC) {
            load_chunk((c + 2) % 3, c + 2);
            CP_WAIT2();
        } else {
            CP_WAIT0();
        }
        __syncthreads();

        const uint32_t stb = sm_base + (uint32_t)(c % 3) * 32768u;
        const uint32_t Ah = stb, Al = stb + 8192u, Bh = stb + 16384u, Bl = stb + 24576u;

#pragma unroll
        for (int kt = 0; kt < 2; kt++) {
            uint32_t ahf[2][4], alf[2][4], bhf[4][4], blf[4][4];
#pragma unroll
            for (int mt = 0; mt < 2; mt++) {
                uint32_t off = sw64((a_row + mt * 16) * 64 + kt * 32 + a_c16 * 16);
                ldsm4(ahf[mt], Ah + off);
                ldsm4(alf[mt], Al + off);
            }
#pragma unroll
            for (int p = 0; p < 4; p++) {
                uint32_t off = sw64((b_row + p * 16) * 64 + kt * 32 + b_c16 * 16);
                ldsm4(bhf[p], Bh + off);
                ldsm4(blf[p], Bl + off);
            }
#pragma unroll
            for (int mt = 0; mt < 2; mt++)
#pragma unroll
                for (int nt = 0; nt < 8; nt++)
                    mma16816(acc[mt][nt], ahf[mt], &bhf[nt >> 1][(nt & 1) * 2]);
#pragma unroll
            for (int mt = 0; mt < 2; mt++)
#pragma unroll
                for (int nt = 0; nt < 8; nt++)
                    mma16816(acc[mt][nt], ahf[mt], &blf[nt >> 1][(nt & 1) * 2]);
#pragma unroll
            for (int mt = 0; mt < 2; mt++)
#pragma unroll
                for (int nt = 0; nt < 8; nt++)
                    mma16816(acc[mt][nt], alf[mt], &bhf[nt >> 1][(nt & 1) * 2]);
        }
        __syncthreads();
    }

    // epilogue: C frag lane mapping: rows l/4 (+8), cols (l%4)*2 (+1)
    const int mr = m0 + wm * 32 + (lane >> 2);
    const int nc = n0 + wn * 64 + (lane & 3) * 2;
#pragma unroll
    for (int mt = 0; mt < 2; mt++) {
#pragma unroll
        for (int nt = 0; nt < 8; nt++) {
#pragma unroll
            for (int half = 0; half < 2; half++) {
                const int m = mr + mt * 16 + half * 8;
                const int n = nc + nt * 8;
                float2 v = make_float2(acc[mt][nt][half * 2], acc[mt][nt][half * 2 + 1]);
                if (MODE == 0) {
                    *(float2*)&C[(size_t)m * N + n] = v;
                } else {
                    const int b = m >> 11;
                    const int s = m & (SEQ - 1);
                    const int h = n >> 7;
                    const int d = n & (HD - 1);
                    *(float2*)&C[((size_t)(b * nh + h) * SEQ + s) * HD + d] = v;
                }
            }
        }
    }
}

// ---------------------------------------------------------------------------
// RoPE (in place) on [B, nh, S, HD]; pair (d, d+64)
// ---------------------------------------------------------------------------
__global__ void rope_kernel(float* __restrict__ x,
                            const float* __restrict__ cosb,
                            const float* __restrict__ sinb, int nh, int total)
{
    int idx = blockIdx.x * blockDim.x + threadIdx.x;
    if (idx >= total) return;
    const int d = idx & 63;
    const int row = idx >> 6;
    const int s = row & (SEQ - 1);
    const int b = (row / SEQ) / nh;
    float* xr = x + (size_t)row * HD;
    const float* cb = cosb + ((size_t)b * SEQ + s) * HD;
    const float* sb = sinb + ((size_t)b * SEQ + s) * HD;
    const float x0 = xr[d];
    const float x1 = xr[d + 64];
    xr[d]      = x0 * cb[d]      - x1 * sb[d];
    xr[d + 64] = x1 * cb[d + 64] + x0 * sb[d + 64];
}

// ---------------------------------------------------------------------------
// Flash attention, fp32 (unchanged — next optimization target)
// ---------------------------------------------------------------------------
#define FL_SMEM ((128 * 68 * 2 + 64 * 132 + 64 * 68 + 192) * 4)

__global__ __launch_bounds__(256) void flash_kernel(
    const float* __restrict__ Q, const float* __restrict__ K,
    const float* __restrict__ V, float* __restrict__ O)
{
    extern __shared__ float smem[];
    float* sQt = smem;
    float* sKt = sQt + 128 * 68;
    float* sV  = sKt + 128 * 68;
    float* sS  = sV + 64 * 132;
    float* sM  = sS + 64 * 68;
    float* sL  = sM + 64;
    float* sC  = sL + 64;

    const int tid = threadIdx.x;
    const int nqt = SEQ / 64;
    const int bh = blockIdx.x / nqt;
    const int qt = blockIdx.x % nqt;
    const int b = bh / NHEADS;
    const int h = bh % NHEADS;
    const int kvh = h / NREP;
    const int q0 = qt * 64;

    const float* Qb = Q + (size_t)(b * NHEADS + h) * SEQ * HD;
    const float* Kb = K + (size_t)(b * NKV + kvh) * SEQ * HD;
    const float* Vb = V + (size_t)(b * NKV + kvh) * SEQ * HD;

    for (int e = tid; e < 64 * HD / 4; e += 256) {
        const int r = e >> 5;
        const int d4 = (e & 31) * 4;
        float4 v = *(const float4*)&Qb[(size_t)(q0 + r) * HD + d4];
        sQt[(d4 + 0) * 68 + r] = v.x;
        sQt[(d4 + 1) * 68 + r] = v.y;
        sQt[(d4 + 2) * 68 + r] = v.z;
        sQt[(d4 + 3) * 68 + r] = v.w;
    }
    if (tid < 64) { sM[tid] = -INFINITY; sL[tid] = 0.f; }

    float acc[4][8];
#pragma unroll
    for (int j = 0; j < 4; j++)
#pragma unroll
        for (int i = 0; i < 8; i++) acc[j][i] = 0.f;

    const int rg = tid >> 4;
    const int cg = tid & 15;
    const int r4 = tid >> 2;
    const int t4 = tid & 3;

    const int nkt = qt + 1;
    for (int kt = 0; kt < nkt; kt++) {
        const int k0 = kt * 64;
        __syncthreads();
        for (int e = tid; e < 64 * HD / 4; e += 256) {
            const int r = e >> 5;
            const int d4 = (e & 31) * 4;
            float4 kv = *(const float4*)&Kb[(size_t)(k0 + r) * HD + d4];
            sKt[(d4 + 0) * 68 + r] = kv.x;
            sKt[(d4 + 1) * 68 + r] = kv.y;
            sKt[(d4 + 2) * 68 + r] = kv.z;
            sKt[(d4 + 3) * 68 + r] = kv.w;
            float4 vv = *(const float4*)&Vb[(size_t)(k0 + r) * HD + d4];
            *(float4*)&sV[r * 132 + d4] = vv;
        }
        __syncthreads();

        const int rq = rg * 4;
        const int cq = cg * 4;
        float sc[4][4];
#pragma unroll
        for (int j = 0; j < 4; j++)
#pragma unroll
            for (int i = 0; i < 4; i++) sc[j][i] = 0.f;
#pragma unroll 8
        for (int kk = 0; kk < HD; kk++) {
            float a[4], bb[4];
            *(float4*)a  = *(const float4*)&sQt[kk * 68 + rq];
            *(float4*)bb = *(const float4*)&sKt[kk * 68 + cq];
#pragma unroll
            for (int j = 0; j < 4; j++)
#pragma unroll
                for (int i = 0; i < 4; i++) sc[j][i] = fmaf(a[j], bb[i], sc[j][i]);
        }
#pragma unroll
        for (int j = 0; j < 4; j++)
#pragma unroll
            for (int i = 0; i < 4; i++) {
                float val = sc[j][i] * SCALING;
                if (k0 + cq + i > q0 + rq + j) val = NEG_BIG;
                sS[(rq + j) * 68 + cq + i] = val;
            }
        __syncthreads();

        {
            float lm = -INFINITY;
            const int cbase = t4 * 16;
#pragma unroll
            for (int c = 0; c < 16; c++) lm = fmaxf(lm, sS[r4 * 68 + cbase + c]);
            lm = fmaxf(lm, __shfl_xor_sync(0xffffffffu, lm, 1));
            lm = fmaxf(lm, __shfl_xor_sync(0xffffffffu, lm, 2));
            const float mold = sM[r4];
            const float mnew = fmaxf(mold, lm);
            float lsum = 0.f;
#pragma unroll
            for (int c = 0; c < 16; c++) {
                float p = __expf(sS[r4 * 68 + cbase + c] - mnew);
                sS[r4 * 68 + cbase + c] = p;
                lsum += p;
            }
            lsum += __shfl_xor_sync(0xffffffffu, lsum, 1);
            lsum += __shfl_xor_sync(0xffffffffu, lsum, 2);
            if (t4 == 0) {
                const float corr = __expf(mold - mnew);
                sC[r4] = corr;
                sL[r4] = sL[r4] * corr + lsum;
                sM[r4] = mnew;
            }
        }
        __syncthreads();

#pragma unroll
        for (int j = 0; j < 4; j++) {
            const float corr = sC[rg * 4 + j];
#pragma unroll
            for (int i = 0; i < 8; i++) acc[j][i] *= corr;
        }
        for (int c = 0; c < 64; c += 4) {
            float p[4][4];
#pragma unroll
            for (int j = 0; j < 4; j++) {
                *(float4*)p[j] = *(const float4*)&sS[(rg * 4 + j) * 68 + c];
            }
#pragma unroll
            for (int cc = 0; cc < 4; cc++) {
                float v8[8];
                *(float4*)(v8)     = *(const float4*)&sV[(c + cc) * 132 + cg * 8];
                *(float4*)(v8 + 4) = *(const float4*)&sV[(c + cc) * 132 + cg * 8 + 4];
#pragma unroll
                for (int j = 0; j < 4; j++)
#pragma unroll
                    for (int i = 0; i < 8; i++)
                        acc[j][i] = fmaf(p[j][cc], v8[i], acc[j][i]);
            }
        }
    }

#pragma unroll
    for (int j = 0; j < 4; j++) {
        const int r = rg * 4 + j;
        const float inv = 1.f / sL[r];
        float* op = O + ((size_t)(b * SEQ + q0 + r) * NHEADS + h) * HD + cg * 8;
        float4 o0 = make_float4(acc[j][0] * inv, acc[j][1] * inv, acc[j][2] * inv, acc[j][3] * inv);
        float4 o1 = make_float4(acc[j][4] * inv, acc[j][5] * inv, acc[j][6] * inv, acc[j][7] * inv);
        *(float4*)(op)     = o0;
        *(float4*)(op + 4) = o1;
    }
}

// ---------------------------------------------------------------------------
extern "C" void kernel_launch(void* const* d_in, const int* in_sizes, int n_in,
                              void* d_out, int out_size)
{
    const float* X    = (const float*)d_in[0];
    const float* cosb = (const float*)d_in[1];
    const float* sinb = (const float*)d_in[2];
    const float* wq = (const float*)d_in[4];
    const float* wk = (const float*)d_in[5];
    const float* wv = (const float*)d_in[6];
    const float* wo = (const float*)d_in[7];
    float* out = (float*)d_out;

    void *pq, *pk, *pv, *pa;
    cudaGetSymbolAddress(&pq, g_q);
    cudaGetSymbolAddress(&pk, g_k);
    cudaGetSymbolAddress(&pv, g_v);
    cudaGetSymbolAddress(&pa, g_attn);
    float* Qb = (float*)pq;
    float* Kb = (float*)pk;
    float* Vb = (float*)pv;
    float* Ab = (float*)pa;

    void *pxh, *pxl, *pqh, *pql, *pkh, *pkl, *pvh, *pvl, *poh, *pol, *pah, *pal;
    cudaGetSymbolAddress(&pxh, g_xhi);   cudaGetSymbolAddress(&pxl, g_xlo);
    cudaGetSymbolAddress(&pqh, g_wqT_hi); cudaGetSymbolAddress(&pql, g_wqT_lo);
    cudaGetSymbolAddress(&pkh, g_wkT_hi); cudaGetSymbolAddress(&pkl, g_wkT_lo);
    cudaGetSymbolAddress(&pvh, g_wvT_hi); cudaGetSymbolAddress(&pvl, g_wvT_lo);
    cudaGetSymbolAddress(&poh, g_woT_hi); cudaGetSymbolAddress(&pol, g_woT_lo);
    cudaGetSymbolAddress(&pah, g_ahi);   cudaGetSymbolAddress(&pal, g_alo);
    __nv_bfloat16 *Xhi = (__nv_bfloat16*)pxh, *Xlo = (__nv_bfloat16*)pxl;
    __nv_bfloat16 *WqHi = (__nv_bfloat16*)pqh, *WqLo = (__nv_bfloat16*)pql;
    __nv_bfloat16 *WkHi = (__nv_bfloat16*)pkh, *WkLo = (__nv_bfloat16*)pkl;
    __nv_bfloat16 *WvHi = (__nv_bfloat16*)pvh, *WvLo = (__nv_bfloat16*)pvl;
    __nv_bfloat16 *WoHi = (__nv_bfloat16*)poh, *WoLo = (__nv_bfloat16*)pol;
    __nv_bfloat16 *AtHi = (__nv_bfloat16*)pah, *AtLo = (__nv_bfloat16*)pal;

    static bool attr_set = false;
    if (!attr_set) {
        cudaFuncSetAttribute(flash_kernel, cudaFuncAttributeMaxDynamicSharedMemorySize, FL_SMEM);
        cudaFuncSetAttribute(gemm_mma<0>, cudaFuncAttributeMaxDynamicSharedMemorySize, GT_SMEM);
        cudaFuncSetAttribute(gemm_mma<1>, cudaFuncAttributeMaxDynamicSharedMemorySize, GT_SMEM);
        attr_set = true;
    }

    const int M = BATCH * SEQ;   // 4096

    // Split inputs and weights to bf16 hi/lo (weights transposed to [N,K])
    split_kernel<<<(M * HID / 4 + 255) / 256, 256>>>(X, Xhi, Xlo, M * HID);
    splitT_kernel<<<dim3(4096 / 32, 4096 / 32), dim3(32, 8)>>>(wq, WqHi, WqLo, HID, 4096);
    splitT_kernel<<<dim3(1024 / 32, 4096 / 32), dim3(32, 8)>>>(wk, WkHi, WkLo, HID, 1024);
    splitT_kernel<<<dim3(1024 / 32, 4096 / 32), dim3(32, 8)>>>(wv, WvHi, WvLo, HID, 1024);
    splitT_kernel<<<dim3(4096 / 32, 4096 / 32), dim3(32, 8)>>>(wo, WoHi, WoLo, 4096, HID);

    // Projections on tensor cores (mma.sync; fused layout transform to [b,h,s,d])
    gemm_mma<1><<<dim3(32, 32), 256, GT_SMEM>>>(Xhi, Xlo, WqHi, WqLo, Qb, M, 4096, HID, NHEADS);
    gemm_mma<1><<<dim3(8, 32), 256, GT_SMEM>>>(Xhi, Xlo, WkHi, WkLo, Kb, M, 1024, HID, NKV);
    gemm_mma<1><<<dim3(8, 32), 256, GT_SMEM>>>(Xhi, Xlo, WvHi, WvLo, Vb, M, 1024, HID, NKV);

    // RoPE on Q and K
    {
        int totq = BATCH * NHEADS * SEQ * 64;
        rope_kernel<<<(totq + 255) / 256, 256>>>(Qb, cosb, sinb, NHEADS, totq);
        int totk = BATCH * NKV * SEQ * 64;
        rope_kernel<<<(totk + 255) / 256, 256>>>(Kb, cosb, sinb, NKV, totk);
    }

    // Flash attention -> g_attn [b,s,h,d]
    {
        int nblocks = BATCH * NHEADS * (SEQ / 64);
        flash_kernel<<<nblocks, 256, FL_SMEM>>>(Qb, Kb, Vb, Ab);
    }

    // Output projection on tensor cores
    split_kernel<<<(M * 4096 / 4 + 255) / 256, 256>>>(Ab, AtHi, AtLo, M * 4096);
    gemm_mma<0><<<dim3(32, 32), 256, GT_SMEM>>>(AtHi, AtLo, WoHi, WoLo, out, M, HID, 4096, 0);

    (void)in_sizes; (void)n_in; (void)out_size;
}

// round 4
// speedup vs baseline: 3.0654x; 1.5621x over previous
#include <cuda_runtime.h>
#include <cuda_bf16.h>
#include <math.h>
#include <stdint.h>

// Problem constants
#define BATCH   2
#define SEQ     2048
#define HID     4096
#define NHEADS  32
#define NKV     8
#define NREP    4
#define HD      128
#define SCALING 0.08838834764831845f   // 128^-0.5
#define NEG_BIG (-1.0e30f)

// ---------------------------------------------------------------------------
// Scratch (device globals: allocation-free per harness rules)
// ---------------------------------------------------------------------------
__device__ float g_q[BATCH * NHEADS * SEQ * HD];     // [b,h,s,d]
__device__ float g_k[BATCH * NKV * SEQ * HD];        // [b,kv,s,d]
__device__ float g_v[BATCH * NKV * SEQ * HD];        // [b,kv,s,d]
__device__ float g_attn[BATCH * SEQ * NHEADS * HD];  // [b,s,h,d]

// bf16 split operands for GEMMs
__device__ __nv_bfloat16 g_xhi[4096 * 4096], g_xlo[4096 * 4096];
__device__ __nv_bfloat16 g_wqT_hi[4096 * 4096], g_wqT_lo[4096 * 4096];
__device__ __nv_bfloat16 g_wkT_hi[1024 * 4096], g_wkT_lo[1024 * 4096];
__device__ __nv_bfloat16 g_wvT_hi[1024 * 4096], g_wvT_lo[1024 * 4096];
__device__ __nv_bfloat16 g_woT_hi[4096 * 4096], g_woT_lo[4096 * 4096];
__device__ __nv_bfloat16 g_ahi[4096 * 4096], g_alo[4096 * 4096];

// bf16 split Q/K/V for flash
__device__ __nv_bfloat16 g_qhi[BATCH * NHEADS * SEQ * HD], g_qlo[BATCH * NHEADS * SEQ * HD];
__device__ __nv_bfloat16 g_khi[BATCH * NKV * SEQ * HD],    g_klo[BATCH * NKV * SEQ * HD];
__device__ __nv_bfloat16 g_vhi[BATCH * NKV * SEQ * HD],    g_vlo[BATCH * NKV * SEQ * HD];

// ---------------------------------------------------------------------------
// PTX helpers (portable sm_80-era ops only)
// ---------------------------------------------------------------------------
__device__ __forceinline__ uint32_t smem_u32(const void* p) {
    uint32_t a;
    asm("{ .reg .u64 t; cvta.to.shared.u64 t, %1; cvt.u32.u64 %0, t; }"
        : "=r"(a) : "l"(p));
    return a;
}

#define CP_ASYNC16(dst, src) \
    asm volatile("cp.async.cg.shared.global [%0], [%1], 16;" :: "r"(dst), "l"(src) : "memory")
#define CP_COMMIT() asm volatile("cp.async.commit_group;" ::: "memory")
#define CP_WAIT0()  asm volatile("cp.async.wait_group 0;" ::: "memory")
#define CP_WAIT1()  asm volatile("cp.async.wait_group 1;" ::: "memory")
#define CP_WAIT2()  asm volatile("cp.async.wait_group 2;" ::: "memory")

__device__ __forceinline__ void ldsm4(uint32_t* r, uint32_t addr) {
    asm volatile("ldmatrix.sync.aligned.m8n8.x4.shared.b16 {%0,%1,%2,%3}, [%4];"
        : "=r"(r[0]), "=r"(r[1]), "=r"(r[2]), "=r"(r[3]) : "r"(addr));
}
__device__ __forceinline__ void ldsm4t(uint32_t* r, uint32_t addr) {
    asm volatile("ldmatrix.sync.aligned.m8n8.x4.trans.shared.b16 {%0,%1,%2,%3}, [%4];"
        : "=r"(r[0]), "=r"(r[1]), "=r"(r[2]), "=r"(r[3]) : "r"(addr));
}

__device__ __forceinline__ void mma16816(float* d, const uint32_t* a, const uint32_t* b) {
    asm volatile(
        "mma.sync.aligned.m16n8k16.row.col.f32.bf16.bf16.f32 "
        "{%0,%1,%2,%3}, {%4,%5,%6,%7}, {%8,%9}, {%0,%1,%2,%3};"
        : "+f"(d[0]), "+f"(d[1]), "+f"(d[2]), "+f"(d[3])
        : "r"(a[0]), "r"(a[1]), "r"(a[2]), "r"(a[3]), "r"(b[0]), "r"(b[1]));
}

__device__ __forceinline__ uint32_t sw64(uint32_t off) {
    return off ^ ((off >> 3) & 0x30);
}

__device__ __forceinline__ uint32_t packbf(float lo, float hi) {
    uint32_t r;
    asm("cvt.rn.bf16x2.f32 %0, %1, %2;" : "=r"(r) : "f"(hi), "f"(lo));
    return r;
}

// ---------------------------------------------------------------------------
// Split kernels: fp32 -> bf16 hi/lo
// ---------------------------------------------------------------------------
__global__ void split_kernel(const float* __restrict__ in,
                             __nv_bfloat16* __restrict__ hi,
                             __nv_bfloat16* __restrict__ lo, int n)
{
    int i = (blockIdx.x * blockDim.x + threadIdx.x) * 4;
    if (i >= n) return;
    float4 v = *(const float4*)(in + i);
    float a[4] = {v.x, v.y, v.z, v.w};
    unsigned short hs[4], ls[4];
#pragma unroll
    for (int j = 0; j < 4; j++) {
        __nv_bfloat16 h = __float2bfloat16(a[j]);
        __nv_bfloat16 l = __float2bfloat16(a[j] - __bfloat162float(h));
        hs[j] = *(unsigned short*)&h;
        ls[j] = *(unsigned short*)&l;
    }
    *(ushort4*)(hi + i) = make_ushort4(hs[0], hs[1], hs[2], hs[3]);
    *(ushort4*)(lo + i) = make_ushort4(ls[0], ls[1], ls[2], ls[3]);
}

__global__ void splitT_kernel(const float* __restrict__ in,
                              __nv_bfloat16* __restrict__ hi,
                              __nv_bfloat16* __restrict__ lo, int K, int N)
{
    __shared__ float t[32][33];
    const int k0 = blockIdx.y * 32;
    const int n0 = blockIdx.x * 32;
    const int tx = threadIdx.x, ty = threadIdx.y;
    for (int i = ty; i < 32; i += 8)
        t[i][tx] = in[(size_t)(k0 + i) * N + n0 + tx];
    __syncthreads();
    for (int i = ty; i < 32; i += 8) {
        float a = t[tx][i];
        __nv_bfloat16 h = __float2bfloat16(a);
        __nv_bfloat16 l = __float2bfloat16(a - __bfloat162float(h));
        size_t o = (size_t)(n0 + i) * K + k0 + tx;
        hi[o] = h;
        lo[o] = l;
    }
}

// ---------------------------------------------------------------------------
// mma.sync GEMM (unchanged from round 3)
// ---------------------------------------------------------------------------
#define GT_SMEM (3 * 32768)

template <int MODE>
__global__ __launch_bounds__(256, 1) void gemm_mma(
    const __nv_bfloat16* __restrict__ Ahi, const __nv_bfloat16* __restrict__ Alo,
    const __nv_bfloat16* __restrict__ Bhi, const __nv_bfloat16* __restrict__ Blo,
    float* __restrict__ C, int M, int N, int K, int nh)
{
    extern __shared__ char dsm[];
    const uint32_t sm_base = smem_u32(dsm);

    const int tid = threadIdx.x;
    const int wid = tid >> 5;
    const int lane = tid & 31;
    const int wm = wid & 3;
    const int wn = wid >> 2;
    const int m0 = blockIdx.y * 128;
    const int n0 = blockIdx.x * 128;

    const __nv_bfloat16* srcs[4] = {Ahi, Alo, Bhi, Blo};

    auto load_chunk = [&](int stage, int c) {
        const int k0 = c << 5;
        const uint32_t stb = sm_base + stage * 32768u;
#pragma unroll
        for (int it = 0; it < 8; it++) {
            int g = tid + it * 256;
            int arr = g >> 9;
            int ga = g & 511;
            int r = ga >> 2;
            int cg = ga & 3;
            int rowg = (arr < 2 ? m0 : n0) + r;
            const __nv_bfloat16* src = srcs[arr] + (size_t)rowg * K + k0 + cg * 8;
            uint32_t off = sw64((uint32_t)(r * 64 + cg * 16));
            CP_ASYNC16(stb + arr * 8192u + off, src);
        }
        CP_COMMIT();
    };

    float acc[2][8][4];
#pragma unroll
    for (int mt = 0; mt < 2; mt++)
#pragma unroll
        for (int nt = 0; nt < 8; nt++)
#pragma unroll
            for (int i = 0; i < 4; i++) acc[mt][nt][i] = 0.f;

    const int NC = K >> 5;
    load_chunk(0, 0);
    load_chunk(1, 1);

    const uint32_t a_row = wm * 32 + (lane & 15);
    const uint32_t a_c16 = (lane >> 4);
    const uint32_t b_row = wn * 64 + ((lane >> 4) & 1) * 8 + (lane & 7);
    const uint32_t b_c16 = (lane >> 3) & 1;

    for (int c = 0; c < NC; c++) {
        if (c + 2 < NC) {
            load_chunk((c + 2) % 3, c + 2);
            CP_WAIT2();
        } else {
            CP_WAIT0();
        }
        __syncthreads();

        const uint32_t stb = sm_base + (uint32_t)(c % 3) * 32768u;
        const uint32_t Ah = stb, Al = stb + 8192u, Bh = stb + 16384u, Bl = stb + 24576u;

#pragma unroll
        for (int kt = 0; kt < 2; kt++) {
            uint32_t ahf[2][4], alf[2][4], bhf[4][4], blf[4][4];
#pragma unroll
            for (int mt = 0; mt < 2; mt++) {
                uint32_t off = sw64((a_row + mt * 16) * 64 + kt * 32 + a_c16 * 16);
                ldsm4(ahf[mt], Ah + off);
                ldsm4(alf[mt], Al + off);
            }
#pragma unroll
            for (int p = 0; p < 4; p++) {
                uint32_t off = sw64((b_row + p * 16) * 64 + kt * 32 + b_c16 * 16);
                ldsm4(bhf[p], Bh + off);
                ldsm4(blf[p], Bl + off);
            }
#pragma unroll
            for (int mt = 0; mt < 2; mt++)
#pragma unroll
                for (int nt = 0; nt < 8; nt++)
                    mma16816(acc[mt][nt], ahf[mt], &bhf[nt >> 1][(nt & 1) * 2]);
#pragma unroll
            for (int mt = 0; mt < 2; mt++)
#pragma unroll
                for (int nt = 0; nt < 8; nt++)
                    mma16816(acc[mt][nt], ahf[mt], &blf[nt >> 1][(nt & 1) * 2]);
#pragma unroll
            for (int mt = 0; mt < 2; mt++)
#pragma unroll
                for (int nt = 0; nt < 8; nt++)
                    mma16816(acc[mt][nt], alf[mt], &bhf[nt >> 1][(nt & 1) * 2]);
        }
        __syncthreads();
    }

    const int mr = m0 + wm * 32 + (lane >> 2);
    const int nc = n0 + wn * 64 + (lane & 3) * 2;
#pragma unroll
    for (int mt = 0; mt < 2; mt++) {
#pragma unroll
        for (int nt = 0; nt < 8; nt++) {
#pragma unroll
            for (int half = 0; half < 2; half++) {
                const int m = mr + mt * 16 + half * 8;
                const int n = nc + nt * 8;
                float2 v = make_float2(acc[mt][nt][half * 2], acc[mt][nt][half * 2 + 1]);
                if (MODE == 0) {
                    *(float2*)&C[(size_t)m * N + n] = v;
                } else {
                    const int b = m >> 11;
                    const int s = m & (SEQ - 1);
                    const int h = n >> 7;
                    const int d = n & (HD - 1);
                    *(float2*)&C[((size_t)(b * nh + h) * SEQ + s) * HD + d] = v;
                }
            }
        }
    }
}

// ---------------------------------------------------------------------------
// RoPE (in place) on [B, nh, S, HD]; pair (d, d+64)
// ---------------------------------------------------------------------------
__global__ void rope_kernel(float* __restrict__ x,
                            const float* __restrict__ cosb,
                            const float* __restrict__ sinb, int nh, int total)
{
    int idx = blockIdx.x * blockDim.x + threadIdx.x;
    if (idx >= total) return;
    const int d = idx & 63;
    const int row = idx >> 6;
    const int s = row & (SEQ - 1);
    const int b = (row / SEQ) / nh;
    float* xr = x + (size_t)row * HD;
    const float* cb = cosb + ((size_t)b * SEQ + s) * HD;
    const float* sb = sinb + ((size_t)b * SEQ + s) * HD;
    const float x0 = xr[d];
    const float x1 = xr[d + 64];
    xr[d]      = x0 * cb[d]      - x1 * sb[d];
    xr[d + 64] = x1 * cb[d + 64] + x0 * sb[d + 64];
}

// ---------------------------------------------------------------------------
// Flash attention on mma.sync bf16 with hi/lo splits.
// Br=Bc=64, 128 threads (4 warps x 16 q-rows). Q smem 32KB; KV 2 stages x 64KB.
// Tiles stored as 4 chunks of [64 rows][32 cols bf16] (64B rows, sw64).
// ---------------------------------------------------------------------------
#define FLB_SMEM (32768 + 2 * 65536)

__global__ __launch_bounds__(128) void flash_mma(
    const __nv_bfloat16* __restrict__ Qhi, const __nv_bfloat16* __restrict__ Qlo,
    const __nv_bfloat16* __restrict__ Khi, const __nv_bfloat16* __restrict__ Klo,
    const __nv_bfloat16* __restrict__ Vhi, const __nv_bfloat16* __restrict__ Vlo,
    float* __restrict__ O)
{
    extern __shared__ char dsm[];
    const uint32_t smQ = smem_u32(dsm);

    const int tid = threadIdx.x;
    const int w = tid >> 5;
    const int lane = tid & 31;
    const int bh = blockIdx.x >> 5;
    const int qt = blockIdx.x & 31;
    const int b = bh / NHEADS;
    const int h = bh % NHEADS;
    const int kvh = h / NREP;
    const int q0 = qt * 64;

    const size_t qoff = ((size_t)(b * NHEADS + h) * SEQ + q0) * HD;
    const size_t kvbase = (size_t)(b * NKV + kvh) * SEQ * HD;

    // ---- load Q tile (hi/lo), 2048 granules of 16B ----
    {
#pragma unroll
        for (int it = 0; it < 16; it++) {
            int g = tid + it * 128;
            int arr = g >> 10;
            int rem = g & 1023;
            int r = rem >> 4;
            int gg = rem & 15;
            const __nv_bfloat16* src = (arr ? Qlo : Qhi) + qoff + (size_t)r * HD + gg * 8;
            uint32_t dst = smQ + arr * 16384u + (gg >> 2) * 4096u
                         + sw64((uint32_t)(r * 64 + (gg & 3) * 16));
            CP_ASYNC16(dst, src);
        }
    }

    const __nv_bfloat16* kvsrc[4] = {Khi, Klo, Vhi, Vlo};
    auto load_kv = [&](int stage, int kt) {
        const int k0 = kt * 64;
        const uint32_t stb = smQ + 32768u + stage * 65536u;
#pragma unroll
        for (int it = 0; it < 32; it++) {
            int g = tid + it * 128;
            int arr = g >> 10;
            int rem = g & 1023;
            int r = rem >> 4;
            int gg = rem & 15;
            const __nv_bfloat16* src = kvsrc[arr] + kvbase + (size_t)(k0 + r) * HD + gg * 8;
            uint32_t dst = stb + arr * 16384u + (gg >> 2) * 4096u
                         + sw64((uint32_t)(r * 64 + (gg & 3) * 16));
            CP_ASYNC16(dst, src);
        }
        CP_COMMIT();
    };

    load_kv(0, 0);   // Q granules ride in this first group too

    float o[16][4];
#pragma unroll
    for (int nt = 0; nt < 16; nt++)
#pragma unroll
        for (int e = 0; e < 4; e++) o[nt][e] = 0.f;
    float m_prev[2] = {NEG_BIG, NEG_BIG};
    float l[2] = {0.f, 0.f};

    // ldmatrix address components
    const uint32_t a_row = w * 16 + (lane & 15);
    const uint32_t a_c16 = (lane >> 4) * 16;
    const uint32_t b_row = ((lane >> 4) & 1) * 8 + (lane & 7);
    const uint32_t b_c16 = ((lane >> 3) & 1) * 16;
    const uint32_t v_row = (lane & 7) + ((lane >> 3) & 1) * 8;
    const uint32_t v_c16 = (lane >> 4) * 16;

    const int nkt = qt + 1;
    for (int kt = 0; kt < nkt; kt++) {
        if (kt + 1 < nkt) {
            load_kv((kt + 1) & 1, kt + 1);
            CP_WAIT1();
        } else {
            CP_WAIT0();
        }
        __syncthreads();

        const uint32_t stb = smQ + 32768u + (uint32_t)(kt & 1) * 65536u;
        const uint32_t Kh = stb, Kl = stb + 16384u, Vh = stb + 32768u, Vl = stb + 49152u;

        // ---- S = Q K^T (3-pass split) ----
        float s[8][4];
#pragma unroll
        for (int j = 0; j < 8; j++)
#pragma unroll
            for (int e = 0; e < 4; e++) s[j][e] = 0.f;

#pragma unroll
        for (int ks = 0; ks < 8; ks++) {
            const uint32_t qoffb = (ks >> 1) * 4096u
                + sw64(a_row * 64 + (ks & 1) * 32 + a_c16);
            uint32_t qh[4], ql[4];
            ldsm4(qh, smQ + qoffb);
            ldsm4(ql, smQ + 16384u + qoffb);
            uint32_t kh[4][4], klf[4][4];
#pragma unroll
            for (int p = 0; p < 4; p++) {
                const uint32_t koffb = (ks >> 1) * 4096u
                    + sw64((b_row + p * 16) * 64 + (ks & 1) * 32 + b_c16);
                ldsm4(kh[p], Kh + koffb);
                ldsm4(klf[p], Kl + koffb);
            }
#pragma unroll
            for (int j = 0; j < 8; j++)
                mma16816(s[j], qh, &kh[j >> 1][(j & 1) * 2]);
#pragma unroll
            for (int j = 0; j < 8; j++)
                mma16816(s[j], qh, &klf[j >> 1][(j & 1) * 2]);
#pragma unroll
            for (int j = 0; j < 8; j++)
                mma16816(s[j], ql, &kh[j >> 1][(j & 1) * 2]);
        }

        // ---- softmax (registers) ----
        const bool diag = (kt == qt);
        const int rr0 = w * 16 + (lane >> 2);   // local within 64 only needs lane part
#pragma unroll
        for (int j = 0; j < 8; j++) {
#pragma unroll
            for (int e = 0; e < 4; e++) {
                float val = s[j][e] * SCALING;
                if (diag) {
                    const int cc = j * 8 + (lane & 3) * 2 + (e & 1);
                    const int rloc = w * 16 + (lane >> 2) + (e >> 1) * 8;
                    if (cc > rloc) val = NEG_BIG;
                }
                s[j][e] = val;
            }
        }
        (void)rr0;

        float mx0 = NEG_BIG, mx1 = NEG_BIG;
#pragma unroll
        for (int j = 0; j < 8; j++) {
            mx0 = fmaxf(mx0, fmaxf(s[j][0], s[j][1]));
            mx1 = fmaxf(mx1, fmaxf(s[j][2], s[j][3]));
        }
        mx0 = fmaxf(mx0, __shfl_xor_sync(0xffffffffu, mx0, 1));
        mx0 = fmaxf(mx0, __shfl_xor_sync(0xffffffffu, mx0, 2));
        mx1 = fmaxf(mx1, __shfl_xor_sync(0xffffffffu, mx1, 1));
        mx1 = fmaxf(mx1, __shfl_xor_sync(0xffffffffu, mx1, 2));

        const float mn0 = fmaxf(m_prev[0], mx0);
        const float mn1 = fmaxf(m_prev[1], mx1);
        const float corr0 = __expf(m_prev[0] - mn0);
        const float corr1 = __expf(m_prev[1] - mn1);
        m_prev[0] = mn0;
        m_prev[1] = mn1;

        float rs0 = 0.f, rs1 = 0.f;
#pragma unroll
        for (int j = 0; j < 8; j++) {
            s[j][0] = __expf(s[j][0] - mn0);
            s[j][1] = __expf(s[j][1] - mn0);
            s[j][2] = __expf(s[j][2] - mn1);
            s[j][3] = __expf(s[j][3] - mn1);
            rs0 += s[j][0] + s[j][1];
            rs1 += s[j][2] + s[j][3];
        }
        rs0 += __shfl_xor_sync(0xffffffffu, rs0, 1);
        rs0 += __shfl_xor_sync(0xffffffffu, rs0, 2);
        rs1 += __shfl_xor_sync(0xffffffffu, rs1, 1);
        rs1 += __shfl_xor_sync(0xffffffffu, rs1, 2);
        l[0] = l[0] * corr0 + rs0;
        l[1] = l[1] * corr1 + rs1;

        // rescale O
#pragma unroll
        for (int nt = 0; nt < 16; nt++) {
            o[nt][0] *= corr0; o[nt][1] *= corr0;
            o[nt][2] *= corr1; o[nt][3] *= corr1;
        }

        // pack P (hi/lo split) into A-frags
        uint32_t phi[4][4], plo[4][4];
#pragma unroll
        for (int kk = 0; kk < 4; kk++) {
            const int j0 = 2 * kk, j1 = 2 * kk + 1;
            float hf[8], lf[8];
#pragma unroll
            for (int e = 0; e < 4; e++) {
                float p0 = s[j0][e];
                float h0 = __bfloat162float(__float2bfloat16(p0));
                hf[e] = h0; lf[e] = p0 - h0;
                float p1 = s[j1][e];
                float h1 = __bfloat162float(__float2bfloat16(p1));
                hf[4 + e] = h1; lf[4 + e] = p1 - h1;
            }
            phi[kk][0] = packbf(hf[0], hf[1]);
            phi[kk][1] = packbf(hf[2], hf[3]);
            phi[kk][2] = packbf(hf[4], hf[5]);
            phi[kk][3] = packbf(hf[6], hf[7]);
            plo[kk][0] = packbf(lf[0], lf[1]);
            plo[kk][1] = packbf(lf[2], lf[3]);
            plo[kk][2] = packbf(lf[4], lf[5]);
            plo[kk][3] = packbf(lf[6], lf[7]);
        }

        // ---- O += P V (3-pass split) ----
#pragma unroll
        for (int c = 0; c < 4; c++) {
#pragma unroll
            for (int ks = 0; ks < 4; ks++) {
                uint32_t vh0[4], vh1[4], vl0[4], vl1[4];
                const uint32_t vb0 = c * 4096u + sw64((ks * 16 + v_row) * 64 + v_c16);
                const uint32_t vb1 = c * 4096u + sw64((ks * 16 + v_row) * 64 + 32 + v_c16);
                ldsm4t(vh0, Vh + vb0);
                ldsm4t(vh1, Vh + vb1);
                ldsm4t(vl0, Vl + vb0);
                ldsm4t(vl1, Vl + vb1);
                mma16816(o[c * 4 + 0], phi[ks], vh0 + 0);
                mma16816(o[c * 4 + 1], phi[ks], vh0 + 2);
                mma16816(o[c * 4 + 2], phi[ks], vh1 + 0);
                mma16816(o[c * 4 + 3], phi[ks], vh1 + 2);
                mma16816(o[c * 4 + 0], phi[ks], vl0 + 0);
                mma16816(o[c * 4 + 1], phi[ks], vl0 + 2);
                mma16816(o[c * 4 + 2], phi[ks], vl1 + 0);
                mma16816(o[c * 4 + 3], phi[ks], vl1 + 2);
                mma16816(o[c * 4 + 0], plo[ks], vh0 + 0);
                mma16816(o[c * 4 + 1], plo[ks], vh0 + 2);
                mma16816(o[c * 4 + 2], plo[ks], vh1 + 0);
                mma16816(o[c * 4 + 3], plo[ks], vh1 + 2);
            }
        }
        __syncthreads();
    }

    // ---- epilogue: normalize, write [b, s, h, d] fp32 ----
    const float inv0 = 1.f / l[0];
    const float inv1 = 1.f / l[1];
    const int row0 = q0 + w * 16 + (lane >> 2);
#pragma unroll
    for (int nt = 0; nt < 16; nt++) {
        const int d = nt * 8 + (lane & 3) * 2;
        float* p0 = O + ((size_t)(b * SEQ + row0) * NHEADS + h) * HD + d;
        float* p1 = O + ((size_t)(b * SEQ + row0 + 8) * NHEADS + h) * HD + d;
        *(float2*)p0 = make_float2(o[nt][0] * inv0, o[nt][1] * inv0);
        *(float2*)p1 = make_float2(o[nt][2] * inv1, o[nt][3] * inv1);
    }
}

// ---------------------------------------------------------------------------
extern "C" void kernel_launch(void* const* d_in, const int* in_sizes, int n_in,
                              void* d_out, int out_size)
{
    const float* X    = (const float*)d_in[0];
    const float* cosb = (const float*)d_in[1];
    const float* sinb = (const float*)d_in[2];
    const float* wq = (const float*)d_in[4];
    const float* wk = (const float*)d_in[5];
    const float* wv = (const float*)d_in[6];
    const float* wo = (const float*)d_in[7];
    float* out = (float*)d_out;

    void *pq, *pk, *pv, *pa;
    cudaGetSymbolAddress(&pq, g_q);
    cudaGetSymbolAddress(&pk, g_k);
    cudaGetSymbolAddress(&pv, g_v);
    cudaGetSymbolAddress(&pa, g_attn);
    float* Qb = (float*)pq;
    float* Kb = (float*)pk;
    float* Vb = (float*)pv;
    float* Ab = (float*)pa;

    void *pxh, *pxl, *pqh, *pql, *pkh, *pkl, *pvh, *pvl, *poh, *pol, *pah, *pal;
    cudaGetSymbolAddress(&pxh, g_xhi);   cudaGetSymbolAddress(&pxl, g_xlo);
    cudaGetSymbolAddress(&pqh, g_wqT_hi); cudaGetSymbolAddress(&pql, g_wqT_lo);
    cudaGetSymbolAddress(&pkh, g_wkT_hi); cudaGetSymbolAddress(&pkl, g_wkT_lo);
    cudaGetSymbolAddress(&pvh, g_wvT_hi); cudaGetSymbolAddress(&pvl, g_wvT_lo);
    cudaGetSymbolAddress(&poh, g_woT_hi); cudaGetSymbolAddress(&pol, g_woT_lo);
    cudaGetSymbolAddress(&pah, g_ahi);   cudaGetSymbolAddress(&pal, g_alo);
    __nv_bfloat16 *Xhi = (__nv_bfloat16*)pxh, *Xlo = (__nv_bfloat16*)pxl;
    __nv_bfloat16 *WqHi = (__nv_bfloat16*)pqh, *WqLo = (__nv_bfloat16*)pql;
    __nv_bfloat16 *WkHi = (__nv_bfloat16*)pkh, *WkLo = (__nv_bfloat16*)pkl;
    __nv_bfloat16 *WvHi = (__nv_bfloat16*)pvh, *WvLo = (__nv_bfloat16*)pvl;
    __nv_bfloat16 *WoHi = (__nv_bfloat16*)poh, *WoLo = (__nv_bfloat16*)pol;
    __nv_bfloat16 *AtHi = (__nv_bfloat16*)pah, *AtLo = (__nv_bfloat16*)pal;

    void *pfqh, *pfql, *pfkh, *pfkl, *pfvh, *pfvl;
    cudaGetSymbolAddress(&pfqh, g_qhi); cudaGetSymbolAddress(&pfql, g_qlo);
    cudaGetSymbolAddress(&pfkh, g_khi); cudaGetSymbolAddress(&pfkl, g_klo);
    cudaGetSymbolAddress(&pfvh, g_vhi); cudaGetSymbolAddress(&pfvl, g_vlo);
    __nv_bfloat16 *FQh = (__nv_bfloat16*)pfqh, *FQl = (__nv_bfloat16*)pfql;
    __nv_bfloat16 *FKh = (__nv_bfloat16*)pfkh, *FKl = (__nv_bfloat16*)pfkl;
    __nv_bfloat16 *FVh = (__nv_bfloat16*)pfvh, *FVl = (__nv_bfloat16*)pfvl;

    static bool attr_set = false;
    if (!attr_set) {
        cudaFuncSetAttribute(gemm_mma<0>, cudaFuncAttributeMaxDynamicSharedMemorySize, GT_SMEM);
        cudaFuncSetAttribute(gemm_mma<1>, cudaFuncAttributeMaxDynamicSharedMemorySize, GT_SMEM);
        cudaFuncSetAttribute(flash_mma, cudaFuncAttributeMaxDynamicSharedMemorySize, FLB_SMEM);
        attr_set = true;
    }

    const int M = BATCH * SEQ;   // 4096

    // Split inputs and weights to bf16 hi/lo (weights transposed to [N,K])
    split_kernel<<<(M * HID / 4 + 255) / 256, 256>>>(X, Xhi, Xlo, M * HID);
    splitT_kernel<<<dim3(4096 / 32, 4096 / 32), dim3(32, 8)>>>(wq, WqHi, WqLo, HID, 4096);
    splitT_kernel<<<dim3(1024 / 32, 4096 / 32), dim3(32, 8)>>>(wk, WkHi, WkLo, HID, 1024);
    splitT_kernel<<<dim3(1024 / 32, 4096 / 32), dim3(32, 8)>>>(wv, WvHi, WvLo, HID, 1024);
    splitT_kernel<<<dim3(4096 / 32, 4096 / 32), dim3(32, 8)>>>(wo, WoHi, WoLo, 4096, HID);

    // Projections on tensor cores (fused layout transform to [b,h,s,d])
    gemm_mma<1><<<dim3(32, 32), 256, GT_SMEM>>>(Xhi, Xlo, WqHi, WqLo, Qb, M, 4096, HID, NHEADS);
    gemm_mma<1><<<dim3(8, 32), 256, GT_SMEM>>>(Xhi, Xlo, WkHi, WkLo, Kb, M, 1024, HID, NKV);
    gemm_mma<1><<<dim3(8, 32), 256, GT_SMEM>>>(Xhi, Xlo, WvHi, WvLo, Vb, M, 1024, HID, NKV);

    // RoPE on Q and K
    {
        int totq = BATCH * NHEADS * SEQ * 64;
        rope_kernel<<<(totq + 255) / 256, 256>>>(Qb, cosb, sinb, NHEADS, totq);
        int totk = BATCH * NKV * SEQ * 64;
        rope_kernel<<<(totk + 255) / 256, 256>>>(Kb, cosb, sinb, NKV, totk);
    }

    // Split Q/K/V to bf16 hi/lo for the tensor-core flash kernel
    {
        int nq = BATCH * NHEADS * SEQ * HD;
        int nkv = BATCH * NKV * SEQ * HD;
        split_kernel<<<(nq / 4 + 255) / 256, 256>>>(Qb, FQh, FQl, nq);
        split_kernel<<<(nkv / 4 + 255) / 256, 256>>>(Kb, FKh, FKl, nkv);
        split_kernel<<<(nkv / 4 + 255) / 256, 256>>>(Vb, FVh, FVl, nkv);
    }

    // Flash attention (mma.sync) -> g_attn [b,s,h,d]
    flash_mma<<<BATCH * NHEADS * (SEQ / 64), 128, FLB_SMEM>>>(
        FQh, FQl, FKh, FKl, FVh, FVl, Ab);

    // Output projection on tensor cores
    split_kernel<<<(M * 4096 / 4 + 255) / 256, 256>>>(Ab, AtHi, AtLo, M * 4096);
    gemm_mma<0><<<dim3(32, 32), 256, GT_SMEM>>>(AtHi, AtLo, WoHi, WoLo, out, M, HID, 4096, 0);

    (void)in_sizes; (void)n_in; (void)out_size;
}

// round 5
// speedup vs baseline: 3.1864x; 1.0395x over previous
#include <cuda_runtime.h>
#include <cuda_bf16.h>
#include <math.h>
#include <stdint.h>

// Problem constants
#define BATCH   2
#define SEQ     2048
#define HID     4096
#define NHEADS  32
#define NKV     8
#define NREP    4
#define HD      128
#define SCALING 0.08838834764831845f   // 128^-0.5
#define NEG_BIG (-1.0e30f)

// ---------------------------------------------------------------------------
// Scratch (device globals)
// ---------------------------------------------------------------------------
__device__ float g_q[BATCH * NHEADS * SEQ * HD];     // [b,h,s,d] (pre-rope fp32)
__device__ float g_k[BATCH * NKV * SEQ * HD];
__device__ float g_v[BATCH * NKV * SEQ * HD];

__device__ __nv_bfloat16 g_xhi[4096 * 4096], g_xlo[4096 * 4096];
__device__ __nv_bfloat16 g_wqT_hi[4096 * 4096], g_wqT_lo[4096 * 4096];
__device__ __nv_bfloat16 g_wkT_hi[1024 * 4096], g_wkT_lo[1024 * 4096];
__device__ __nv_bfloat16 g_wvT_hi[1024 * 4096], g_wvT_lo[1024 * 4096];
__device__ __nv_bfloat16 g_woT_hi[4096 * 4096], g_woT_lo[4096 * 4096];
__device__ __nv_bfloat16 g_ahi[4096 * 4096], g_alo[4096 * 4096];   // attn out hi/lo

__device__ __nv_bfloat16 g_qhi[BATCH * NHEADS * SEQ * HD], g_qlo[BATCH * NHEADS * SEQ * HD];
__device__ __nv_bfloat16 g_khi[BATCH * NKV * SEQ * HD],    g_klo[BATCH * NKV * SEQ * HD];
__device__ __nv_bfloat16 g_vhi[BATCH * NKV * SEQ * HD],    g_vlo[BATCH * NKV * SEQ * HD];

// ---------------------------------------------------------------------------
// PTX helpers (portable sm_80-era ops only)
// ---------------------------------------------------------------------------
__device__ __forceinline__ uint32_t smem_u32(const void* p) {
    uint32_t a;
    asm("{ .reg .u64 t; cvta.to.shared.u64 t, %1; cvt.u32.u64 %0, t; }"
        : "=r"(a) : "l"(p));
    return a;
}

#define CP_ASYNC16(dst, src) \
    asm volatile("cp.async.cg.shared.global [%0], [%1], 16;" :: "r"(dst), "l"(src) : "memory")
#define CP_COMMIT() asm volatile("cp.async.commit_group;" ::: "memory")
#define CP_WAIT0()  asm volatile("cp.async.wait_group 0;" ::: "memory")
#define CP_WAIT1()  asm volatile("cp.async.wait_group 1;" ::: "memory")
#define CP_WAIT2()  asm volatile("cp.async.wait_group 2;" ::: "memory")

__device__ __forceinline__ void ldsm4(uint32_t* r, uint32_t addr) {
    asm volatile("ldmatrix.sync.aligned.m8n8.x4.shared.b16 {%0,%1,%2,%3}, [%4];"
        : "=r"(r[0]), "=r"(r[1]), "=r"(r[2]), "=r"(r[3]) : "r"(addr));
}
__device__ __forceinline__ void ldsm4t(uint32_t* r, uint32_t addr) {
    asm volatile("ldmatrix.sync.aligned.m8n8.x4.trans.shared.b16 {%0,%1,%2,%3}, [%4];"
        : "=r"(r[0]), "=r"(r[1]), "=r"(r[2]), "=r"(r[3]) : "r"(addr));
}

__device__ __forceinline__ void mma16816(float* d, const uint32_t* a, const uint32_t* b) {
    asm volatile(
        "mma.sync.aligned.m16n8k16.row.col.f32.bf16.bf16.f32 "
        "{%0,%1,%2,%3}, {%4,%5,%6,%7}, {%8,%9}, {%0,%1,%2,%3};"
        : "+f"(d[0]), "+f"(d[1]), "+f"(d[2]), "+f"(d[3])
        : "r"(a[0]), "r"(a[1]), "r"(a[2]), "r"(a[3]), "r"(b[0]), "r"(b[1]));
}

__device__ __forceinline__ uint32_t sw64(uint32_t off) {
    return off ^ ((off >> 3) & 0x30);
}

__device__ __forceinline__ uint32_t packbf(float lo, float hi) {
    uint32_t r;
    asm("cvt.rn.bf16x2.f32 %0, %1, %2;" : "=r"(r) : "f"(hi), "f"(lo));
    return r;
}

// ---------------------------------------------------------------------------
// Split kernels
// ---------------------------------------------------------------------------
__global__ void split_kernel(const float* __restrict__ in,
                             __nv_bfloat16* __restrict__ hi,
                             __nv_bfloat16* __restrict__ lo, int n)
{
    int i = (blockIdx.x * blockDim.x + threadIdx.x) * 4;
    if (i >= n) return;
    float4 v = *(const float4*)(in + i);
    float a[4] = {v.x, v.y, v.z, v.w};
    unsigned short hs[4], ls[4];
#pragma unroll
    for (int j = 0; j < 4; j++) {
        __nv_bfloat16 h = __float2bfloat16(a[j]);
        __nv_bfloat16 l = __float2bfloat16(a[j] - __bfloat162float(h));
        hs[j] = *(unsigned short*)&h;
        ls[j] = *(unsigned short*)&l;
    }
    *(ushort4*)(hi + i) = make_ushort4(hs[0], hs[1], hs[2], hs[3]);
    *(ushort4*)(lo + i) = make_ushort4(ls[0], ls[1], ls[2], ls[3]);
}

__global__ void splitT_kernel(const float* __restrict__ in,
                              __nv_bfloat16* __restrict__ hi,
                              __nv_bfloat16* __restrict__ lo, int K, int N)
{
    __shared__ float t[32][33];
    const int k0 = blockIdx.y * 32;
    const int n0 = blockIdx.x * 32;
    const int tx = threadIdx.x, ty = threadIdx.y;
    for (int i = ty; i < 32; i += 8)
        t[i][tx] = in[(size_t)(k0 + i) * N + n0 + tx];
    __syncthreads();
    for (int i = ty; i < 32; i += 8) {
        float a = t[tx][i];
        __nv_bfloat16 h = __float2bfloat16(a);
        __nv_bfloat16 l = __float2bfloat16(a - __bfloat162float(h));
        size_t o = (size_t)(n0 + i) * K + k0 + tx;
        hi[o] = h;
        lo[o] = l;
    }
}

// RoPE + split fused: read fp32 [b,nh,s,d], write bf16 hi/lo (same layout)
__global__ void rope_split(const float* __restrict__ x,
                           const float* __restrict__ cosb,
                           const float* __restrict__ sinb,
                           __nv_bfloat16* __restrict__ hi,
                           __nv_bfloat16* __restrict__ lo, int nh, int total)
{
    int idx = blockIdx.x * blockDim.x + threadIdx.x;
    if (idx >= total) return;
    const int d = idx & 63;
    const int row = idx >> 6;
    const int s = row & (SEQ - 1);
    const int b = (row / SEQ) / nh;
    const float* xr = x + (size_t)row * HD;
    const float* cb = cosb + ((size_t)b * SEQ + s) * HD;
    const float* sb = sinb + ((size_t)b * SEQ + s) * HD;
    const float x0 = xr[d];
    const float x1 = xr[d + 64];
    const float y0 = x0 * cb[d]      - x1 * sb[d];
    const float y1 = x1 * cb[d + 64] + x0 * sb[d + 64];
    const size_t o = (size_t)row * HD + d;
    __nv_bfloat16 h0 = __float2bfloat16(y0);
    __nv_bfloat16 h1 = __float2bfloat16(y1);
    hi[o]      = h0;
    hi[o + 64] = h1;
    lo[o]      = __float2bfloat16(y0 - __bfloat162float(h0));
    lo[o + 64] = __float2bfloat16(y1 - __bfloat162float(h1));
}

// ---------------------------------------------------------------------------
// mma.sync GEMM (unchanged)
// ---------------------------------------------------------------------------
#define GT_SMEM (3 * 32768)

template <int MODE>
__global__ __launch_bounds__(256, 1) void gemm_mma(
    const __nv_bfloat16* __restrict__ Ahi, const __nv_bfloat16* __restrict__ Alo,
    const __nv_bfloat16* __restrict__ Bhi, const __nv_bfloat16* __restrict__ Blo,
    float* __restrict__ C, int M, int N, int K, int nh)
{
    extern __shared__ char dsm[];
    const uint32_t sm_base = smem_u32(dsm);

    const int tid = threadIdx.x;
    const int wid = tid >> 5;
    const int lane = tid & 31;
    const int wm = wid & 3;
    const int wn = wid >> 2;
    const int m0 = blockIdx.y * 128;
    const int n0 = blockIdx.x * 128;

    const __nv_bfloat16* srcs[4] = {Ahi, Alo, Bhi, Blo};

    auto load_chunk = [&](int stage, int c) {
        const int k0 = c << 5;
        const uint32_t stb = sm_base + stage * 32768u;
#pragma unroll
        for (int it = 0; it < 8; it++) {
            int g = tid + it * 256;
            int arr = g >> 9;
            int ga = g & 511;
            int r = ga >> 2;
            int cg = ga & 3;
            int rowg = (arr < 2 ? m0 : n0) + r;
            const __nv_bfloat16* src = srcs[arr] + (size_t)rowg * K + k0 + cg * 8;
            uint32_t off = sw64((uint32_t)(r * 64 + cg * 16));
            CP_ASYNC16(stb + arr * 8192u + off, src);
        }
        CP_COMMIT();
    };

    float acc[2][8][4];
#pragma unroll
    for (int mt = 0; mt < 2; mt++)
#pragma unroll
        for (int nt = 0; nt < 8; nt++)
#pragma unroll
            for (int i = 0; i < 4; i++) acc[mt][nt][i] = 0.f;

    const int NC = K >> 5;
    load_chunk(0, 0);
    load_chunk(1, 1);

    const uint32_t a_row = wm * 32 + (lane & 15);
    const uint32_t a_c16 = (lane >> 4);
    const uint32_t b_row = wn * 64 + ((lane >> 4) & 1) * 8 + (lane & 7);
    const uint32_t b_c16 = (lane >> 3) & 1;

    for (int c = 0; c < NC; c++) {
        if (c + 2 < NC) {
            load_chunk((c + 2) % 3, c + 2);
            CP_WAIT2();
        } else {
            CP_WAIT0();
        }
        __syncthreads();

        const uint32_t stb = sm_base + (uint32_t)(c % 3) * 32768u;
        const uint32_t Ah = stb, Al = stb + 8192u, Bh = stb + 16384u, Bl = stb + 24576u;

#pragma unroll
        for (int kt = 0; kt < 2; kt++) {
            uint32_t ahf[2][4], alf[2][4], bhf[4][4], blf[4][4];
#pragma unroll
            for (int mt = 0; mt < 2; mt++) {
                uint32_t off = sw64((a_row + mt * 16) * 64 + kt * 32 + a_c16 * 16);
                ldsm4(ahf[mt], Ah + off);
                ldsm4(alf[mt], Al + off);
            }
#pragma unroll
            for (int p = 0; p < 4; p++) {
                uint32_t off = sw64((b_row + p * 16) * 64 + kt * 32 + b_c16 * 16);
                ldsm4(bhf[p], Bh + off);
                ldsm4(blf[p], Bl + off);
            }
#pragma unroll
            for (int mt = 0; mt < 2; mt++)
#pragma unroll
                for (int nt = 0; nt < 8; nt++)
                    mma16816(acc[mt][nt], ahf[mt], &bhf[nt >> 1][(nt & 1) * 2]);
#pragma unroll
            for (int mt = 0; mt < 2; mt++)
#pragma unroll
                for (int nt = 0; nt < 8; nt++)
                    mma16816(acc[mt][nt], ahf[mt], &blf[nt >> 1][(nt & 1) * 2]);
#pragma unroll
            for (int mt = 0; mt < 2; mt++)
#pragma unroll
                for (int nt = 0; nt < 8; nt++)
                    mma16816(acc[mt][nt], alf[mt], &bhf[nt >> 1][(nt & 1) * 2]);
        }
        __syncthreads();
    }

    const int mr = m0 + wm * 32 + (lane >> 2);
    const int nc = n0 + wn * 64 + (lane & 3) * 2;
#pragma unroll
    for (int mt = 0; mt < 2; mt++) {
#pragma unroll
        for (int nt = 0; nt < 8; nt++) {
#pragma unroll
            for (int half = 0; half < 2; half++) {
                const int m = mr + mt * 16 + half * 8;
                const int n = nc + nt * 8;
                float2 v = make_float2(acc[mt][nt][half * 2], acc[mt][nt][half * 2 + 1]);
                if (MODE == 0) {
                    *(float2*)&C[(size_t)m * N + n] = v;
                } else {
                    const int b = m >> 11;
                    const int s = m & (SEQ - 1);
                    const int h = n >> 7;
                    const int d = n & (HD - 1);
                    *(float2*)&C[((size_t)(b * nh + h) * SEQ + s) * HD + d] = v;
                }
            }
        }
    }
}

// ---------------------------------------------------------------------------
// Flash attention v2: Br=128, Bc=64, 256 threads (8 warps x 16 q-rows).
// Q smem 64KB (hi/lo); KV 2 stages x 64KB. Longest-first CTA order.
// Epilogue writes attn output directly as bf16 hi/lo [b,s,h,d].
// ---------------------------------------------------------------------------
#define FLB_SMEM (65536 + 2 * 65536)
#define NQT (SEQ / 128)   // 16

__global__ __launch_bounds__(256) void flash_mma(
    const __nv_bfloat16* __restrict__ Qhi, const __nv_bfloat16* __restrict__ Qlo,
    const __nv_bfloat16* __restrict__ Khi, const __nv_bfloat16* __restrict__ Klo,
    const __nv_bfloat16* __restrict__ Vhi, const __nv_bfloat16* __restrict__ Vlo,
    __nv_bfloat16* __restrict__ Ohi, __nv_bfloat16* __restrict__ Olo)
{
    extern __shared__ char dsm[];
    const uint32_t smQ = smem_u32(dsm);
    const uint32_t smKV = smQ + 65536u;

    const int tid = threadIdx.x;
    const int w = tid >> 5;
    const int lane = tid & 31;
    const int qt = NQT - 1 - blockIdx.x;   // longest first
    const int bh = blockIdx.y;
    const int b = bh / NHEADS;
    const int h = bh % NHEADS;
    const int kvh = h / NREP;
    const int q0 = qt * 128;

    const size_t qoff = ((size_t)(b * NHEADS + h) * SEQ + q0) * HD;
    const size_t kvbase = (size_t)(b * NKV + kvh) * SEQ * HD;

    // ---- load Q tile (hi/lo): 2 arr x 128 rows x 16 granules = 4096 / 256 threads
    {
#pragma unroll
        for (int it = 0; it < 16; it++) {
            int g = tid + it * 256;
            int arr = g >> 11;
            int rem = g & 2047;
            int r = rem >> 4;
            int gg = rem & 15;
            const __nv_bfloat16* src = (arr ? Qlo : Qhi) + qoff + (size_t)r * HD + gg * 8;
            uint32_t dst = smQ + arr * 32768u + (gg >> 2) * 8192u
                         + sw64((uint32_t)(r * 64 + (gg & 3) * 16));
            CP_ASYNC16(dst, src);
        }
    }

    const __nv_bfloat16* kvsrc[4] = {Khi, Klo, Vhi, Vlo};
    auto load_kv = [&](int stage, int kt) {
        const int k0 = kt * 64;
        const uint32_t stb = smKV + stage * 65536u;
#pragma unroll
        for (int it = 0; it < 16; it++) {
            int g = tid + it * 256;
            int arr = g >> 10;
            int rem = g & 1023;
            int r = rem >> 4;
            int gg = rem & 15;
            const __nv_bfloat16* src = kvsrc[arr] + kvbase + (size_t)(k0 + r) * HD + gg * 8;
            uint32_t dst = stb + arr * 16384u + (gg >> 2) * 4096u
                         + sw64((uint32_t)(r * 64 + (gg & 3) * 16));
            CP_ASYNC16(dst, src);
        }
        CP_COMMIT();
    };

    load_kv(0, 0);   // Q granules ride in this group

    float o[16][4];
#pragma unroll
    for (int nt = 0; nt < 16; nt++)
#pragma unroll
        for (int e = 0; e < 4; e++) o[nt][e] = 0.f;
    float m_prev[2] = {NEG_BIG, NEG_BIG};
    float l[2] = {0.f, 0.f};

    const uint32_t a_row = w * 16 + (lane & 15);
    const uint32_t a_c16 = (lane >> 4) * 16;
    const uint32_t b_row = ((lane >> 4) & 1) * 8 + (lane & 7);
    const uint32_t b_c16 = ((lane >> 3) & 1) * 16;
    const uint32_t v_row = (lane & 7) + ((lane >> 3) & 1) * 8;
    const uint32_t v_c16 = (lane >> 4) * 16;

    const int nkt = 2 * qt + 2;
    for (int kt = 0; kt < nkt; kt++) {
        if (kt + 1 < nkt) {
            load_kv((kt + 1) & 1, kt + 1);
            CP_WAIT1();
        } else {
            CP_WAIT0();
        }
        __syncthreads();

        const uint32_t stb = smKV + (uint32_t)(kt & 1) * 65536u;
        const uint32_t Kh = stb, Kl = stb + 16384u, Vh = stb + 32768u, Vl = stb + 49152u;

        // ---- S = Q K^T (3-pass split) ----
        float s[8][4];
#pragma unroll
        for (int j = 0; j < 8; j++)
#pragma unroll
            for (int e = 0; e < 4; e++) s[j][e] = 0.f;

#pragma unroll
        for (int ks = 0; ks < 8; ks++) {
            const uint32_t qoffb = (ks >> 1) * 8192u
                + sw64(a_row * 64 + (ks & 1) * 32 + a_c16);
            uint32_t qh[4], ql[4];
            ldsm4(qh, smQ + qoffb);
            ldsm4(ql, smQ + 32768u + qoffb);
            uint32_t kh[4][4], klf[4][4];
#pragma unroll
            for (int p = 0; p < 4; p++) {
                const uint32_t koffb = (ks >> 1) * 4096u
                    + sw64((b_row + p * 16) * 64 + (ks & 1) * 32 + b_c16);
                ldsm4(kh[p], Kh + koffb);
                ldsm4(klf[p], Kl + koffb);
            }
#pragma unroll
            for (int j = 0; j < 8; j++)
                mma16816(s[j], qh, &kh[j >> 1][(j & 1) * 2]);
#pragma unroll
            for (int j = 0; j < 8; j++)
                mma16816(s[j], qh, &klf[j >> 1][(j & 1) * 2]);
#pragma unroll
            for (int j = 0; j < 8; j++)
                mma16816(s[j], ql, &kh[j >> 1][(j & 1) * 2]);
        }

        // ---- softmax (registers) ----
        const bool diag = (kt >= nkt - 2);
        const int k0 = kt * 64;
#pragma unroll
        for (int j = 0; j < 8; j++) {
#pragma unroll
            for (int e = 0; e < 4; e++) {
                float val = s[j][e] * SCALING;
                if (diag) {
                    const int cglob = k0 + j * 8 + (lane & 3) * 2 + (e & 1);
                    const int rglob = q0 + w * 16 + (lane >> 2) + (e >> 1) * 8;
                    if (cglob > rglob) val = NEG_BIG;
                }
                s[j][e] = val;
            }
        }

        float mx0 = NEG_BIG, mx1 = NEG_BIG;
#pragma unroll
        for (int j = 0; j < 8; j++) {
            mx0 = fmaxf(mx0, fmaxf(s[j][0], s[j][1]));
            mx1 = fmaxf(mx1, fmaxf(s[j][2], s[j][3]));
        }
        mx0 = fmaxf(mx0, __shfl_xor_sync(0xffffffffu, mx0, 1));
        mx0 = fmaxf(mx0, __shfl_xor_sync(0xffffffffu, mx0, 2));
        mx1 = fmaxf(mx1, __shfl_xor_sync(0xffffffffu, mx1, 1));
        mx1 = fmaxf(mx1, __shfl_xor_sync(0xffffffffu, mx1, 2));

        const float mn0 = fmaxf(m_prev[0], mx0);
        const float mn1 = fmaxf(m_prev[1], mx1);
        const float corr0 = __expf(m_prev[0] - mn0);
        const float corr1 = __expf(m_prev[1] - mn1);
        m_prev[0] = mn0;
        m_prev[1] = mn1;

        float rs0 = 0.f, rs1 = 0.f;
#pragma unroll
        for (int j = 0; j < 8; j++) {
            s[j][0] = __expf(s[j][0] - mn0);
            s[j][1] = __expf(s[j][1] - mn0);
            s[j][2] = __expf(s[j][2] - mn1);
            s[j][3] = __expf(s[j][3] - mn1);
            rs0 += s[j][0] + s[j][1];
            rs1 += s[j][2] + s[j][3];
        }
        rs0 += __shfl_xor_sync(0xffffffffu, rs0, 1);
        rs0 += __shfl_xor_sync(0xffffffffu, rs0, 2);
        rs1 += __shfl_xor_sync(0xffffffffu, rs1, 1);
        rs1 += __shfl_xor_sync(0xffffffffu, rs1, 2);
        l[0] = l[0] * corr0 + rs0;
        l[1] = l[1] * corr1 + rs1;

#pragma unroll
        for (int nt = 0; nt < 16; nt++) {
            o[nt][0] *= corr0; o[nt][1] *= corr0;
            o[nt][2] *= corr1; o[nt][3] *= corr1;
        }

        // pack P (hi/lo split) into A-frags
        uint32_t phi[4][4], plo[4][4];
#pragma unroll
        for (int kk = 0; kk < 4; kk++) {
            const int j0 = 2 * kk, j1 = 2 * kk + 1;
            float hf[8], lf[8];
#pragma unroll
            for (int e = 0; e < 4; e++) {
                float p0 = s[j0][e];
                float h0 = __bfloat162float(__float2bfloat16(p0));
                hf[e] = h0; lf[e] = p0 - h0;
                float p1 = s[j1][e];
                float h1 = __bfloat162float(__float2bfloat16(p1));
                hf[4 + e] = h1; lf[4 + e] = p1 - h1;
            }
            phi[kk][0] = packbf(hf[0], hf[1]);
            phi[kk][1] = packbf(hf[2], hf[3]);
            phi[kk][2] = packbf(hf[4], hf[5]);
            phi[kk][3] = packbf(hf[6], hf[7]);
            plo[kk][0] = packbf(lf[0], lf[1]);
            plo[kk][1] = packbf(lf[2], lf[3]);
            plo[kk][2] = packbf(lf[4], lf[5]);
            plo[kk][3] = packbf(lf[6], lf[7]);
        }

        // ---- O += P V (3-pass split) ----
#pragma unroll
        for (int c = 0; c < 4; c++) {
#pragma unroll
            for (int ks = 0; ks < 4; ks++) {
                uint32_t vh0[4], vh1[4], vl0[4], vl1[4];
                const uint32_t vb0 = c * 4096u + sw64((ks * 16 + v_row) * 64 + v_c16);
                const uint32_t vb1 = c * 4096u + sw64((ks * 16 + v_row) * 64 + 32 + v_c16);
                ldsm4t(vh0, Vh + vb0);
                ldsm4t(vh1, Vh + vb1);
                ldsm4t(vl0, Vl + vb0);
                ldsm4t(vl1, Vl + vb1);
                mma16816(o[c * 4 + 0], phi[ks], vh0 + 0);
                mma16816(o[c * 4 + 1], phi[ks], vh0 + 2);
                mma16816(o[c * 4 + 2], phi[ks], vh1 + 0);
                mma16816(o[c * 4 + 3], phi[ks], vh1 + 2);
                mma16816(o[c * 4 + 0], phi[ks], vl0 + 0);
                mma16816(o[c * 4 + 1], phi[ks], vl0 + 2);
                mma16816(o[c * 4 + 2], phi[ks], vl1 + 0);
                mma16816(o[c * 4 + 3], phi[ks], vl1 + 2);
                mma16816(o[c * 4 + 0], plo[ks], vh0 + 0);
                mma16816(o[c * 4 + 1], plo[ks], vh0 + 2);
                mma16816(o[c * 4 + 2], plo[ks], vh1 + 0);
                mma16816(o[c * 4 + 3], plo[ks], vh1 + 2);
            }
        }
        __syncthreads();
    }

    // ---- epilogue: normalize, write attn hi/lo bf16 [b, s, h, d] ----
    const float inv0 = 1.f / l[0];
    const float inv1 = 1.f / l[1];
    const int row0 = q0 + w * 16 + (lane >> 2);
#pragma unroll
    for (int nt = 0; nt < 16; nt++) {
        const int d = nt * 8 + (lane & 3) * 2;
        const size_t o0 = ((size_t)(b * SEQ + row0) * NHEADS + h) * HD + d;
        const size_t o1 = ((size_t)(b * SEQ + row0 + 8) * NHEADS + h) * HD + d;
        float v00 = o[nt][0] * inv0, v01 = o[nt][1] * inv0;
        float v10 = o[nt][2] * inv1, v11 = o[nt][3] * inv1;
        __nv_bfloat16 h00 = __float2bfloat16(v00), h01 = __float2bfloat16(v01);
        __nv_bfloat16 h10 = __float2bfloat16(v10), h11 = __float2bfloat16(v11);
        *(uint32_t*)&Ohi[o0] = packbf(__bfloat162float(h00) * 0.f + v00, v01);  // rn pack
        *(uint32_t*)&Ohi[o1] = packbf(v10, v11);
        *(uint32_t*)&Olo[o0] = packbf(v00 - __bfloat162float(h00), v01 - __bfloat162float(h01));
        *(uint32_t*)&Olo[o1] = packbf(v10 - __bfloat162float(h10), v11 - __bfloat162float(h11));
    }
}

// ---------------------------------------------------------------------------
extern "C" void kernel_launch(void* const* d_in, const int* in_sizes, int n_in,
                              void* d_out, int out_size)
{
    const float* X    = (const float*)d_in[0];
    const float* cosb = (const float*)d_in[1];
    const float* sinb = (const float*)d_in[2];
    const float* wq = (const float*)d_in[4];
    const float* wk = (const float*)d_in[5];
    const float* wv = (const float*)d_in[6];
    const float* wo = (const float*)d_in[7];
    float* out = (float*)d_out;

    void *pq, *pk, *pv;
    cudaGetSymbolAddress(&pq, g_q);
    cudaGetSymbolAddress(&pk, g_k);
    cudaGetSymbolAddress(&pv, g_v);
    float* Qb = (float*)pq;
    float* Kb = (float*)pk;
    float* Vb = (float*)pv;

    void *pxh, *pxl, *pqh, *pql, *pkh, *pkl, *pvh, *pvl, *poh, *pol, *pah, *pal;
    cudaGetSymbolAddress(&pxh, g_xhi);   cudaGetSymbolAddress(&pxl, g_xlo);
    cudaGetSymbolAddress(&pqh, g_wqT_hi); cudaGetSymbolAddress(&pql, g_wqT_lo);
    cudaGetSymbolAddress(&pkh, g_wkT_hi); cudaGetSymbolAddress(&pkl, g_wkT_lo);
    cudaGetSymbolAddress(&pvh, g_wvT_hi); cudaGetSymbolAddress(&pvl, g_wvT_lo);
    cudaGetSymbolAddress(&poh, g_woT_hi); cudaGetSymbolAddress(&pol, g_woT_lo);
    cudaGetSymbolAddress(&pah, g_ahi);   cudaGetSymbolAddress(&pal, g_alo);
    __nv_bfloat16 *Xhi = (__nv_bfloat16*)pxh, *Xlo = (__nv_bfloat16*)pxl;
    __nv_bfloat16 *WqHi = (__nv_bfloat16*)pqh, *WqLo = (__nv_bfloat16*)pql;
    __nv_bfloat16 *WkHi = (__nv_bfloat16*)pkh, *WkLo = (__nv_bfloat16*)pkl;
    __nv_bfloat16 *WvHi = (__nv_bfloat16*)pvh, *WvLo = (__nv_bfloat16*)pvl;
    __nv_bfloat16 *WoHi = (__nv_bfloat16*)poh, *WoLo = (__nv_bfloat16*)pol;
    __nv_bfloat16 *AtHi = (__nv_bfloat16*)pah, *AtLo = (__nv_bfloat16*)pal;

    void *pfqh, *pfql, *pfkh, *pfkl, *pfvh, *pfvl;
    cudaGetSymbolAddress(&pfqh, g_qhi); cudaGetSymbolAddress(&pfql, g_qlo);
    cudaGetSymbolAddress(&pfkh, g_khi); cudaGetSymbolAddress(&pfkl, g_klo);
    cudaGetSymbolAddress(&pfvh, g_vhi); cudaGetSymbolAddress(&pfvl, g_vlo);
    __nv_bfloat16 *FQh = (__nv_bfloat16*)pfqh, *FQl = (__nv_bfloat16*)pfql;
    __nv_bfloat16 *FKh = (__nv_bfloat16*)pfkh, *FKl = (__nv_bfloat16*)pfkl;
    __nv_bfloat16 *FVh = (__nv_bfloat16*)pfvh, *FVl = (__nv_bfloat16*)pfvl;

    static bool attr_set = false;
    if (!attr_set) {
        cudaFuncSetAttribute(gemm_mma<0>, cudaFuncAttributeMaxDynamicSharedMemorySize, GT_SMEM);
        cudaFuncSetAttribute(gemm_mma<1>, cudaFuncAttributeMaxDynamicSharedMemorySize, GT_SMEM);
        cudaFuncSetAttribute(flash_mma, cudaFuncAttributeMaxDynamicSharedMemorySize, FLB_SMEM);
        attr_set = true;
    }

    const int M = BATCH * SEQ;   // 4096

    // Split inputs and weights to bf16 hi/lo (weights transposed to [N,K])
    split_kernel<<<(M * HID / 4 + 255) / 256, 256>>>(X, Xhi, Xlo, M * HID);
    splitT_kernel<<<dim3(4096 / 32, 4096 / 32), dim3(32, 8)>>>(wq, WqHi, WqLo, HID, 4096);
    splitT_kernel<<<dim3(1024 / 32, 4096 / 32), dim3(32, 8)>>>(wk, WkHi, WkLo, HID, 1024);
    splitT_kernel<<<dim3(1024 / 32, 4096 / 32), dim3(32, 8)>>>(wv, WvHi, WvLo, HID, 1024);
    splitT_kernel<<<dim3(4096 / 32, 4096 / 32), dim3(32, 8)>>>(wo, WoHi, WoLo, 4096, HID);

    // Projections on tensor cores (fused layout transform to [b,h,s,d])
    gemm_mma<1><<<dim3(32, 32), 256, GT_SMEM>>>(Xhi, Xlo, WqHi, WqLo, Qb, M, 4096, HID, NHEADS);
    gemm_mma<1><<<dim3(8, 32), 256, GT_SMEM>>>(Xhi, Xlo, WkHi, WkLo, Kb, M, 1024, HID, NKV);
    gemm_mma<1><<<dim3(8, 32), 256, GT_SMEM>>>(Xhi, Xlo, WvHi, WvLo, Vb, M, 1024, HID, NKV);

    // RoPE + split fused for Q/K; plain split for V
    {
        int totq = BATCH * NHEADS * SEQ * 64;
        rope_split<<<(totq + 255) / 256, 256>>>(Qb, cosb, sinb, FQh, FQl, NHEADS, totq);
        int totk = BATCH * NKV * SEQ * 64;
        rope_split<<<(totk + 255) / 256, 256>>>(Kb, cosb, sinb, FKh, FKl, NKV, totk);
        int nkv = BATCH * NKV * SEQ * HD;
        split_kernel<<<(nkv / 4 + 255) / 256, 256>>>(Vb, FVh, FVl, nkv);
    }

    // Flash attention (mma.sync) -> attn hi/lo [b,s,h,d]
    flash_mma<<<dim3(NQT, BATCH * NHEADS), 256, FLB_SMEM>>>(
        FQh, FQl, FKh, FKl, FVh, FVl, AtHi, AtLo);

    // Output projection on tensor cores
    gemm_mma<0><<<dim3(32, 32), 256, GT_SMEM>>>(AtHi, AtLo, WoHi, WoLo, out, M, HID, 4096, 0);

    (void)in_sizes; (void)n_in; (void)out_size;
}

// round 7
// speedup vs baseline: 3.2234x; 1.0116x over previous
#include <cuda_runtime.h>
#include <cuda_bf16.h>
#include <math.h>
#include <stdint.h>

// Problem constants
#define BATCH   2
#define SEQ     2048
#define HID     4096
#define NHEADS  32
#define NKV     8
#define NREP    4
#define HD      128
#define SCALING 0.08838834764831845f           // 128^-0.5
#define QSCALE  0.1275429555686623f            // SCALING * log2(e)
#define NEG_BIG (-1.0e30f)

// ---------------------------------------------------------------------------
// Scratch (device globals)
// ---------------------------------------------------------------------------
__device__ float g_q[BATCH * NHEADS * SEQ * HD];
__device__ float g_k[BATCH * NKV * SEQ * HD];
__device__ float g_v[BATCH * NKV * SEQ * HD];

__device__ __nv_bfloat16 g_xhi[4096 * 4096], g_xlo[4096 * 4096];
__device__ __nv_bfloat16 g_wqT_hi[4096 * 4096], g_wqT_lo[4096 * 4096];
__device__ __nv_bfloat16 g_wkT_hi[1024 * 4096], g_wkT_lo[1024 * 4096];
__device__ __nv_bfloat16 g_wvT_hi[1024 * 4096], g_wvT_lo[1024 * 4096];
__device__ __nv_bfloat16 g_woT_hi[4096 * 4096], g_woT_lo[4096 * 4096];
__device__ __nv_bfloat16 g_ahi[4096 * 4096], g_alo[4096 * 4096];

__device__ __nv_bfloat16 g_qhi[BATCH * NHEADS * SEQ * HD], g_qlo[BATCH * NHEADS * SEQ * HD];
__device__ __nv_bfloat16 g_khi[BATCH * NKV * SEQ * HD],    g_klo[BATCH * NKV * SEQ * HD];
__device__ __nv_bfloat16 g_vhi[BATCH * NKV * SEQ * HD],    g_vlo[BATCH * NKV * SEQ * HD];

// ---------------------------------------------------------------------------
// PTX helpers
// ---------------------------------------------------------------------------
__device__ __forceinline__ uint32_t smem_u32(const void* p) {
    uint32_t a;
    asm("{ .reg .u64 t; cvta.to.shared.u64 t, %1; cvt.u32.u64 %0, t; }"
        : "=r"(a) : "l"(p));
    return a;
}

#define CP_ASYNC16(dst, src) \
    asm volatile("cp.async.cg.shared.global [%0], [%1], 16;" :: "r"(dst), "l"(src) : "memory")
#define CP_COMMIT() asm volatile("cp.async.commit_group;" ::: "memory")
#define CP_WAIT0()  asm volatile("cp.async.wait_group 0;" ::: "memory")
#define CP_WAIT1()  asm volatile("cp.async.wait_group 1;" ::: "memory")
#define CP_WAIT2()  asm volatile("cp.async.wait_group 2;" ::: "memory")

__device__ __forceinline__ void ldsm4(uint32_t* r, uint32_t addr) {
    asm volatile("ldmatrix.sync.aligned.m8n8.x4.shared.b16 {%0,%1,%2,%3}, [%4];"
        : "=r"(r[0]), "=r"(r[1]), "=r"(r[2]), "=r"(r[3]) : "r"(addr));
}
__device__ __forceinline__ void ldsm4t(uint32_t* r, uint32_t addr) {
    asm volatile("ldmatrix.sync.aligned.m8n8.x4.trans.shared.b16 {%0,%1,%2,%3}, [%4];"
        : "=r"(r[0]), "=r"(r[1]), "=r"(r[2]), "=r"(r[3]) : "r"(addr));
}

__device__ __forceinline__ void mma16816(float* d, const uint32_t* a, const uint32_t* b) {
    asm volatile(
        "mma.sync.aligned.m16n8k16.row.col.f32.bf16.bf16.f32 "
        "{%0,%1,%2,%3}, {%4,%5,%6,%7}, {%8,%9}, {%0,%1,%2,%3};"
        : "+f"(d[0]), "+f"(d[1]), "+f"(d[2]), "+f"(d[3])
        : "r"(a[0]), "r"(a[1]), "r"(a[2]), "r"(a[3]), "r"(b[0]), "r"(b[1]));
}

__device__ __forceinline__ uint32_t sw64(uint32_t off) {
    return off ^ ((off >> 3) & 0x30);
}

__device__ __forceinline__ uint32_t packbf(float lo, float hi) {
    uint32_t r;
    asm("cvt.rn.bf16x2.f32 %0, %1, %2;" : "=r"(r) : "f"(hi), "f"(lo));
    return r;
}

__device__ __forceinline__ float ex2(float x) {
    float r;
    asm("ex2.approx.f32 %0, %1;" : "=f"(r) : "f"(x));
    return r;
}

// ---------------------------------------------------------------------------
// Split kernels
// ---------------------------------------------------------------------------
__global__ void split_kernel(const float* __restrict__ in,
                             __nv_bfloat16* __restrict__ hi,
                             __nv_bfloat16* __restrict__ lo, int n)
{
    int i = (blockIdx.x * blockDim.x + threadIdx.x) * 4;
    if (i >= n) return;
    float4 v = *(const float4*)(in + i);
    float a[4] = {v.x, v.y, v.z, v.w};
    unsigned short hs[4], ls[4];
#pragma unroll
    for (int j = 0; j < 4; j++) {
        __nv_bfloat16 h = __float2bfloat16(a[j]);
        __nv_bfloat16 l = __float2bfloat16(a[j] - __bfloat162float(h));
        hs[j] = *(unsigned short*)&h;
        ls[j] = *(unsigned short*)&l;
    }
    *(ushort4*)(hi + i) = make_ushort4(hs[0], hs[1], hs[2], hs[3]);
    *(ushort4*)(lo + i) = make_ushort4(ls[0], ls[1], ls[2], ls[3]);
}

__global__ void splitT_kernel(const float* __restrict__ in,
                              __nv_bfloat16* __restrict__ hi,
                              __nv_bfloat16* __restrict__ lo, int K, int N)
{
    __shared__ float t[32][33];
    const int k0 = blockIdx.y * 32;
    const int n0 = blockIdx.x * 32;
    const int tx = threadIdx.x, ty = threadIdx.y;
    for (int i = ty; i < 32; i += 8)
        t[i][tx] = in[(size_t)(k0 + i) * N + n0 + tx];
    __syncthreads();
    for (int i = ty; i < 32; i += 8) {
        float a = t[tx][i];
        __nv_bfloat16 h = __float2bfloat16(a);
        __nv_bfloat16 l = __float2bfloat16(a - __bfloat162float(h));
        size_t o = (size_t)(n0 + i) * K + k0 + tx;
        hi[o] = h;
        lo[o] = l;
    }
}

// RoPE + scale + split fused
__global__ void rope_split(const float* __restrict__ x,
                           const float* __restrict__ cosb,
                           const float* __restrict__ sinb,
                           __nv_bfloat16* __restrict__ hi,
                           __nv_bfloat16* __restrict__ lo,
                           int nh, int total, float scale)
{
    int idx = blockIdx.x * blockDim.x + threadIdx.x;
    if (idx >= total) return;
    const int d = idx & 63;
    const int row = idx >> 6;
    const int s = row & (SEQ - 1);
    const int b = (row / SEQ) / nh;
    const float* xr = x + (size_t)row * HD;
    const float* cb = cosb + ((size_t)b * SEQ + s) * HD;
    const float* sb = sinb + ((size_t)b * SEQ + s) * HD;
    const float x0 = xr[d];
    const float x1 = xr[d + 64];
    const float y0 = (x0 * cb[d]      - x1 * sb[d])      * scale;
    const float y1 = (x1 * cb[d + 64] + x0 * sb[d + 64]) * scale;
    const size_t o = (size_t)row * HD + d;
    __nv_bfloat16 h0 = __float2bfloat16(y0);
    __nv_bfloat16 h1 = __float2bfloat16(y1);
    hi[o]      = h0;
    hi[o + 64] = h1;
    lo[o]      = __float2bfloat16(y0 - __bfloat162float(h0));
    lo[o + 64] = __float2bfloat16(y1 - __bfloat162float(h1));
}

// ---------------------------------------------------------------------------
// mma.sync GEMM (unchanged)
// ---------------------------------------------------------------------------
#define GT_SMEM (3 * 32768)

template <int MODE>
__global__ __launch_bounds__(256, 1) void gemm_mma(
    const __nv_bfloat16* __restrict__ Ahi, const __nv_bfloat16* __restrict__ Alo,
    const __nv_bfloat16* __restrict__ Bhi, const __nv_bfloat16* __restrict__ Blo,
    float* __restrict__ C, int M, int N, int K, int nh)
{
    extern __shared__ char dsm[];
    const uint32_t sm_base = smem_u32(dsm);

    const int tid = threadIdx.x;
    const int wid = tid >> 5;
    const int lane = tid & 31;
    const int wm = wid & 3;
    const int wn = wid >> 2;
    const int m0 = blockIdx.y * 128;
    const int n0 = blockIdx.x * 128;

    const __nv_bfloat16* srcs[4] = {Ahi, Alo, Bhi, Blo};

    auto load_chunk = [&](int stage, int c) {
        const int k0 = c << 5;
        const uint32_t stb = sm_base + stage * 32768u;
#pragma unroll
        for (int it = 0; it < 8; it++) {
            int g = tid + it * 256;
            int arr = g >> 9;
            int ga = g & 511;
            int r = ga >> 2;
            int cg = ga & 3;
            int rowg = (arr < 2 ? m0 : n0) + r;
            const __nv_bfloat16* src = srcs[arr] + (size_t)rowg * K + k0 + cg * 8;
            uint32_t off = sw64((uint32_t)(r * 64 + cg * 16));
            CP_ASYNC16(stb + arr * 8192u + off, src);
        }
        CP_COMMIT();
    };

    float acc[2][8][4];
#pragma unroll
    for (int mt = 0; mt < 2; mt++)
#pragma unroll
        for (int nt = 0; nt < 8; nt++)
#pragma unroll
            for (int i = 0; i < 4; i++) acc[mt][nt][i] = 0.f;

    const int NC = K >> 5;
    load_chunk(0, 0);
    load_chunk(1, 1);

    const uint32_t a_row = wm * 32 + (lane & 15);
    const uint32_t a_c16 = (lane >> 4);
    const uint32_t b_row = wn * 64 + ((lane >> 4) & 1) * 8 + (lane & 7);
    const uint32_t b_c16 = (lane >> 3) & 1;

    for (int c = 0; c < NC; c++) {
        if (c + 2 < NC) {
            load_chunk((c + 2) % 3, c + 2);
            CP_WAIT2();
        } else {
            CP_WAIT0();
        }
        __syncthreads();

        const uint32_t stb = sm_base + (uint32_t)(c % 3) * 32768u;
        const uint32_t Ah = stb, Al = stb + 8192u, Bh = stb + 16384u, Bl = stb + 24576u;

#pragma unroll
        for (int kt = 0; kt < 2; kt++) {
            uint32_t ahf[2][4], alf[2][4], bhf[4][4], blf[4][4];
#pragma unroll
            for (int mt = 0; mt < 2; mt++) {
                uint32_t off = sw64((a_row + mt * 16) * 64 + kt * 32 + a_c16 * 16);
                ldsm4(ahf[mt], Ah + off);
                ldsm4(alf[mt], Al + off);
            }
#pragma unroll
            for (int p = 0; p < 4; p++) {
                uint32_t off = sw64((b_row + p * 16) * 64 + kt * 32 + b_c16 * 16);
                ldsm4(bhf[p], Bh + off);
                ldsm4(blf[p], Bl + off);
            }
#pragma unroll
            for (int mt = 0; mt < 2; mt++)
#pragma unroll
                for (int nt = 0; nt < 8; nt++)
                    mma16816(acc[mt][nt], ahf[mt], &bhf[nt >> 1][(nt & 1) * 2]);
#pragma unroll
            for (int mt = 0; mt < 2; mt++)
#pragma unroll
                for (int nt = 0; nt < 8; nt++)
                    mma16816(acc[mt][nt], ahf[mt], &blf[nt >> 1][(nt & 1) * 2]);
#pragma unroll
            for (int mt = 0; mt < 2; mt++)
#pragma unroll
                for (int nt = 0; nt < 8; nt++)
                    mma16816(acc[mt][nt], alf[mt], &bhf[nt >> 1][(nt & 1) * 2]);
        }
        __syncthreads();
    }

    const int mr = m0 + wm * 32 + (lane >> 2);
    const int nc = n0 + wn * 64 + (lane & 3) * 2;
#pragma unroll
    for (int mt = 0; mt < 2; mt++) {
#pragma unroll
        for (int nt = 0; nt < 8; nt++) {
#pragma unroll
            for (int half = 0; half < 2; half++) {
                const int m = mr + mt * 16 + half * 8;
                const int n = nc + nt * 8;
                float2 v = make_float2(acc[mt][nt][half * 2], acc[mt][nt][half * 2 + 1]);
                if (MODE == 0) {
                    *(float2*)&C[(size_t)m * N + n] = v;
                } else {
                    const int b = m >> 11;
                    const int s = m & (SEQ - 1);
                    const int h = n >> 7;
                    const int d = n & (HD - 1);
                    *(float2*)&C[((size_t)(b * nh + h) * SEQ + s) * HD + d] = v;
                }
            }
        }
    }
}

// ---------------------------------------------------------------------------
// Flash attention v3 (fixed loaders): Br=128, Bc=64, 256 threads.
// Pipelined: QK(i+1) MMAs issued before softmax(i).
// Separate K and V rings (2 stages x 32KB). Q 64KB. Total 192KB.
// ---------------------------------------------------------------------------
#define FLB_SMEM (196608)
#define NQT (SEQ / 128)   // 16

__global__ __launch_bounds__(256) void flash_mma(
    const __nv_bfloat16* __restrict__ Qhi, const __nv_bfloat16* __restrict__ Qlo,
    const __nv_bfloat16* __restrict__ Khi, const __nv_bfloat16* __restrict__ Klo,
    const __nv_bfloat16* __restrict__ Vhi, const __nv_bfloat16* __restrict__ Vlo,
    __nv_bfloat16* __restrict__ Ohi, __nv_bfloat16* __restrict__ Olo)
{
    extern __shared__ char dsm[];
    const uint32_t smQ = smem_u32(dsm);
    const uint32_t smK = smQ + 65536u;       // 2 stages x 32KB
    const uint32_t smV = smK + 65536u;       // 2 stages x 32KB

    const int tid = threadIdx.x;
    const int w = tid >> 5;
    const int lane = tid & 31;
    const int qt = NQT - 1 - blockIdx.x;     // longest first
    const int bh = blockIdx.y;
    const int b = bh / NHEADS;
    const int h = bh % NHEADS;
    const int kvh = h / NREP;
    const int q0 = qt * 128;

    const size_t qoff = ((size_t)(b * NHEADS + h) * SEQ + q0) * HD;
    const size_t kvbase = (size_t)(b * NKV + kvh) * SEQ * HD;

    // one K/V stage: 2 arrays (hi,lo) x 64 rows x 16 granules = 2048 granules
    auto load_K = [&](int stage, int kt) {
        const int k0 = kt * 64;
        const uint32_t stb = smK + stage * 32768u;
#pragma unroll
        for (int it = 0; it < 8; it++) {
            int g = tid + it * 256;
            int arr = g >> 10;
            int rem = g & 1023;
            int r = rem >> 4;
            int gg = rem & 15;
            const __nv_bfloat16* src = (arr ? Klo : Khi) + kvbase + (size_t)(k0 + r) * HD + gg * 8;
            uint32_t dst = stb + arr * 16384u + (gg >> 2) * 4096u
                         + sw64((uint32_t)(r * 64 + (gg & 3) * 16));
            CP_ASYNC16(dst, src);
        }
    };
    auto load_V = [&](int stage, int kt) {
        const int k0 = kt * 64;
        const uint32_t stb = smV + stage * 32768u;
#pragma unroll
        for (int it = 0; it < 8; it++) {
            int g = tid + it * 256;
            int arr = g >> 10;
            int rem = g & 1023;
            int r = rem >> 4;
            int gg = rem & 15;
            const __nv_bfloat16* src = (arr ? Vlo : Vhi) + kvbase + (size_t)(k0 + r) * HD + gg * 8;
            uint32_t dst = stb + arr * 16384u + (gg >> 2) * 4096u
                         + sw64((uint32_t)(r * 64 + (gg & 3) * 16));
            CP_ASYNC16(dst, src);
        }
    };

    // ---- prologue: group A = {Q, K0}; group B = {K1, V0} ----
    {
#pragma unroll
        for (int it = 0; it < 16; it++) {
            int g = tid + it * 256;
            int arr = g >> 11;
            int rem = g & 2047;
            int r = rem >> 4;
            int gg = rem & 15;
            const __nv_bfloat16* src = (arr ? Qlo : Qhi) + qoff + (size_t)r * HD + gg * 8;
            uint32_t dst = smQ + arr * 32768u + (gg >> 2) * 8192u
                         + sw64((uint32_t)(r * 64 + (gg & 3) * 16));
            CP_ASYNC16(dst, src);
        }
    }
    load_K(0, 0);
    CP_COMMIT();
    const int nkt = 2 * qt + 2;
    if (nkt > 1) load_K(1, 1);
    load_V(0, 0);
    CP_COMMIT();

    float o[16][4];
#pragma unroll
    for (int nt = 0; nt < 16; nt++)
#pragma unroll
        for (int e = 0; e < 4; e++) o[nt][e] = 0.f;
    float m_prev[2] = {NEG_BIG, NEG_BIG};
    float l[2] = {0.f, 0.f};

    const uint32_t a_row = w * 16 + (lane & 15);
    const uint32_t a_c16 = (lane >> 4) * 16;
    const uint32_t b_row = ((lane >> 4) & 1) * 8 + (lane & 7);
    const uint32_t b_c16 = ((lane >> 3) & 1) * 16;
    const uint32_t v_row = (lane & 7) + ((lane >> 3) & 1) * 8;
    const uint32_t v_c16 = (lane >> 4) * 16;

    float sA[8][4], sB[8][4];

    auto do_qk = [&](int kt, float (*sn)[4]) {
        const uint32_t Kst = smK + (uint32_t)(kt & 1) * 32768u;
        const uint32_t Kh = Kst, Kl = Kst + 16384u;
#pragma unroll
        for (int j = 0; j < 8; j++)
#pragma unroll
            for (int e = 0; e < 4; e++) sn[j][e] = 0.f;
#pragma unroll
        for (int ks = 0; ks < 8; ks++) {
            const uint32_t qoffb = (ks >> 1) * 8192u
                + sw64(a_row * 64 + (ks & 1) * 32 + a_c16);
            uint32_t qh[4], ql[4];
            ldsm4(qh, smQ + qoffb);
            ldsm4(ql, smQ + 32768u + qoffb);
            uint32_t kh[4][4], klf[4][4];
#pragma unroll
            for (int p = 0; p < 4; p++) {
                const uint32_t koffb = (ks >> 1) * 4096u
                    + sw64((b_row + p * 16) * 64 + (ks & 1) * 32 + b_c16);
                ldsm4(kh[p], Kh + koffb);
                ldsm4(klf[p], Kl + koffb);
            }
#pragma unroll
            for (int j = 0; j < 8; j++)
                mma16816(sn[j], qh, &kh[j >> 1][(j & 1) * 2]);
#pragma unroll
            for (int j = 0; j < 8; j++)
                mma16816(sn[j], qh, &klf[j >> 1][(j & 1) * 2]);
#pragma unroll
            for (int j = 0; j < 8; j++)
                mma16816(sn[j], ql, &kh[j >> 1][(j & 1) * 2]);
        }
    };

    auto do_softmax_pv = [&](int kt, float (*s)[4]) {
        const bool diag = (kt >= nkt - 2);
        if (diag) {
            const int k0 = kt * 64;
#pragma unroll
            for (int j = 0; j < 8; j++)
#pragma unroll
                for (int e = 0; e < 4; e++) {
                    const int cglob = k0 + j * 8 + (lane & 3) * 2 + (e & 1);
                    const int rglob = q0 + w * 16 + (lane >> 2) + (e >> 1) * 8;
                    if (cglob > rglob) s[j][e] = NEG_BIG;
                }
        }

        float mx0 = NEG_BIG, mx1 = NEG_BIG;
#pragma unroll
        for (int j = 0; j < 8; j++) {
            mx0 = fmaxf(mx0, fmaxf(s[j][0], s[j][1]));
            mx1 = fmaxf(mx1, fmaxf(s[j][2], s[j][3]));
        }
        mx0 = fmaxf(mx0, __shfl_xor_sync(0xffffffffu, mx0, 1));
        mx0 = fmaxf(mx0, __shfl_xor_sync(0xffffffffu, mx0, 2));
        mx1 = fmaxf(mx1, __shfl_xor_sync(0xffffffffu, mx1, 1));
        mx1 = fmaxf(mx1, __shfl_xor_sync(0xffffffffu, mx1, 2));

        const float mn0 = fmaxf(m_prev[0], mx0);
        const float mn1 = fmaxf(m_prev[1], mx1);
        const float corr0 = ex2(m_prev[0] - mn0);
        const float corr1 = ex2(m_prev[1] - mn1);
        m_prev[0] = mn0;
        m_prev[1] = mn1;

        float rs0 = 0.f, rs1 = 0.f;
#pragma unroll
        for (int j = 0; j < 8; j++) {
            s[j][0] = ex2(s[j][0] - mn0);
            s[j][1] = ex2(s[j][1] - mn0);
            s[j][2] = ex2(s[j][2] - mn1);
            s[j][3] = ex2(s[j][3] - mn1);
            rs0 += s[j][0] + s[j][1];
            rs1 += s[j][2] + s[j][3];
        }
        rs0 += __shfl_xor_sync(0xffffffffu, rs0, 1);
        rs0 += __shfl_xor_sync(0xffffffffu, rs0, 2);
        rs1 += __shfl_xor_sync(0xffffffffu, rs1, 1);
        rs1 += __shfl_xor_sync(0xffffffffu, rs1, 2);
        l[0] = l[0] * corr0 + rs0;
        l[1] = l[1] * corr1 + rs1;

#pragma unroll
        for (int nt = 0; nt < 16; nt++) {
            o[nt][0] *= corr0; o[nt][1] *= corr0;
            o[nt][2] *= corr1; o[nt][3] *= corr1;
        }

        const uint32_t Vst = smV + (uint32_t)(kt & 1) * 32768u;
        const uint32_t Vh = Vst, Vl = Vst + 16384u;
#pragma unroll
        for (int ks = 0; ks < 4; ks++) {
            const int j0 = 2 * ks, j1 = 2 * ks + 1;
            uint32_t phi[4], plo[4];
            {
                float hf[8], lf[8];
#pragma unroll
                for (int e = 0; e < 4; e++) {
                    float p0 = s[j0][e];
                    float h0 = __bfloat162float(__float2bfloat16(p0));
                    hf[e] = h0; lf[e] = p0 - h0;
                    float p1 = s[j1][e];
                    float h1 = __bfloat162float(__float2bfloat16(p1));
                    hf[4 + e] = h1; lf[4 + e] = p1 - h1;
                }
                phi[0] = packbf(hf[0], hf[1]);
                phi[1] = packbf(hf[2], hf[3]);
                phi[2] = packbf(hf[4], hf[5]);
                phi[3] = packbf(hf[6], hf[7]);
                plo[0] = packbf(lf[0], lf[1]);
                plo[1] = packbf(lf[2], lf[3]);
                plo[2] = packbf(lf[4], lf[5]);
                plo[3] = packbf(lf[6], lf[7]);
            }
#pragma unroll
            for (int c = 0; c < 4; c++) {
                uint32_t vh0[4], vh1[4], vl0[4], vl1[4];
                const uint32_t vb0 = c * 4096u + sw64((ks * 16 + v_row) * 64 + v_c16);
                const uint32_t vb1 = c * 4096u + sw64((ks * 16 + v_row) * 64 + 32 + v_c16);
                ldsm4t(vh0, Vh + vb0);
                ldsm4t(vh1, Vh + vb1);
                ldsm4t(vl0, Vl + vb0);
                ldsm4t(vl1, Vl + vb1);
                mma16816(o[c * 4 + 0], phi, vh0 + 0);
                mma16816(o[c * 4 + 1], phi, vh0 + 2);
                mma16816(o[c * 4 + 2], phi, vh1 + 0);
                mma16816(o[c * 4 + 3], phi, vh1 + 2);
                mma16816(o[c * 4 + 0], phi, vl0 + 0);
                mma16816(o[c * 4 + 1], phi, vl0 + 2);
                mma16816(o[c * 4 + 2], phi, vl1 + 0);
                mma16816(o[c * 4 + 3], phi, vl1 + 2);
                mma16816(o[c * 4 + 0], plo, vh0 + 0);
                mma16816(o[c * 4 + 1], plo, vh0 + 2);
                mma16816(o[c * 4 + 2], plo, vh1 + 0);
                mma16816(o[c * 4 + 3], plo, vh1 + 2);
            }
        }
    };

    // first QK: needs group A (Q + K0)
    CP_WAIT1();
    __syncthreads();
    do_qk(0, sA);

    // pipelined body
    auto body = [&](int i, float (*scur)[4], float (*snxt)[4]) {
        CP_WAIT0();
        __syncthreads();
        if (i + 1 < nkt) load_V((i + 1) & 1, i + 1);
        if (i + 2 < nkt) load_K((i + 2) & 1, i + 2);
        CP_COMMIT();
        if (i + 1 < nkt) do_qk(i + 1, snxt);
        do_softmax_pv(i, scur);
    };

    for (int i = 0; i < nkt; i += 2) {
        body(i, sA, sB);
        if (i + 1 < nkt) body(i + 1, sB, sA);
    }

    // ---- epilogue ----
    const float inv0 = 1.f / l[0];
    const float inv1 = 1.f / l[1];
    const int row0 = q0 + w * 16 + (lane >> 2);
#pragma unroll
    for (int nt = 0; nt < 16; nt++) {
        const int d = nt * 8 + (lane & 3) * 2;
        const size_t o0 = ((size_t)(b * SEQ + row0) * NHEADS + h) * HD + d;
        const size_t o1 = ((size_t)(b * SEQ + row0 + 8) * NHEADS + h) * HD + d;
        float v00 = o[nt][0] * inv0, v01 = o[nt][1] * inv0;
        float v10 = o[nt][2] * inv1, v11 = o[nt][3] * inv1;
        __nv_bfloat16 h00 = __float2bfloat16(v00), h01 = __float2bfloat16(v01);
        __nv_bfloat16 h10 = __float2bfloat16(v10), h11 = __float2bfloat16(v11);
        *(uint32_t*)&Ohi[o0] = packbf(v00, v01);
        *(uint32_t*)&Ohi[o1] = packbf(v10, v11);
        *(uint32_t*)&Olo[o0] = packbf(v00 - __bfloat162float(h00), v01 - __bfloat162float(h01));
        *(uint32_t*)&Olo[o1] = packbf(v10 - __bfloat162float(h10), v11 - __bfloat162float(h11));
    }
}

// ---------------------------------------------------------------------------
extern "C" void kernel_launch(void* const* d_in, const int* in_sizes, int n_in,
                              void* d_out, int out_size)
{
    const float* X    = (const float*)d_in[0];
    const float* cosb = (const float*)d_in[1];
    const float* sinb = (const float*)d_in[2];
    const float* wq = (const float*)d_in[4];
    const float* wk = (const float*)d_in[5];
    const float* wv = (const float*)d_in[6];
    const float* wo = (const float*)d_in[7];
    float* out = (float*)d_out;

    void *pq, *pk, *pv;
    cudaGetSymbolAddress(&pq, g_q);
    cudaGetSymbolAddress(&pk, g_k);
    cudaGetSymbolAddress(&pv, g_v);
    float* Qb = (float*)pq;
    float* Kb = (float*)pk;
    float* Vb = (float*)pv;

    void *pxh, *pxl, *pqh, *pql, *pkh, *pkl, *pvh, *pvl, *poh, *pol, *pah, *pal;
    cudaGetSymbolAddress(&pxh, g_xhi);   cudaGetSymbolAddress(&pxl, g_xlo);
    cudaGetSymbolAddress(&pqh, g_wqT_hi); cudaGetSymbolAddress(&pql, g_wqT_lo);
    cudaGetSymbolAddress(&pkh, g_wkT_hi); cudaGetSymbolAddress(&pkl, g_wkT_lo);
    cudaGetSymbolAddress(&pvh, g_wvT_hi); cudaGetSymbolAddress(&pvl, g_wvT_lo);
    cudaGetSymbolAddress(&poh, g_woT_hi); cudaGetSymbolAddress(&pol, g_woT_lo);
    cudaGetSymbolAddress(&pah, g_ahi);   cudaGetSymbolAddress(&pal, g_alo);
    __nv_bfloat16 *Xhi = (__nv_bfloat16*)pxh, *Xlo = (__nv_bfloat16*)pxl;
    __nv_bfloat16 *WqHi = (__nv_bfloat16*)pqh, *WqLo = (__nv_bfloat16*)pql;
    __nv_bfloat16 *WkHi = (__nv_bfloat16*)pkh, *WkLo = (__nv_bfloat16*)pkl;
    __nv_bfloat16 *WvHi = (__nv_bfloat16*)pvh, *WvLo = (__nv_bfloat16*)pvl;
    __nv_bfloat16 *WoHi = (__nv_bfloat16*)poh, *WoLo = (__nv_bfloat16*)pol;
    __nv_bfloat16 *AtHi = (__nv_bfloat16*)pah, *AtLo = (__nv_bfloat16*)pal;

    void *pfqh, *pfql, *pfkh, *pfkl, *pfvh, *pfvl;
    cudaGetSymbolAddress(&pfqh, g_qhi); cudaGetSymbolAddress(&pfql, g_qlo);
    cudaGetSymbolAddress(&pfkh, g_khi); cudaGetSymbolAddress(&pfkl, g_klo);
    cudaGetSymbolAddress(&pfvh, g_vhi); cudaGetSymbolAddress(&pfvl, g_vlo);
    __nv_bfloat16 *FQh = (__nv_bfloat16*)pfqh, *FQl = (__nv_bfloat16*)pfql;
    __nv_bfloat16 *FKh = (__nv_bfloat16*)pfkh, *FKl = (__nv_bfloat16*)pfkl;
    __nv_bfloat16 *FVh = (__nv_bfloat16*)pfvh, *FVl = (__nv_bfloat16*)pfvl;

    static bool attr_set = false;
    if (!attr_set) {
        cudaFuncSetAttribute(gemm_mma<0>, cudaFuncAttributeMaxDynamicSharedMemorySize, GT_SMEM);
        cudaFuncSetAttribute(gemm_mma<1>, cudaFuncAttributeMaxDynamicSharedMemorySize, GT_SMEM);
        cudaFuncSetAttribute(flash_mma, cudaFuncAttributeMaxDynamicSharedMemorySize, FLB_SMEM);
        attr_set = true;
    }

    const int M = BATCH * SEQ;   // 4096

    // Split inputs and weights
    split_kernel<<<(M * HID / 4 + 255) / 256, 256>>>(X, Xhi, Xlo, M * HID);
    splitT_kernel<<<dim3(4096 / 32, 4096 / 32), dim3(32, 8)>>>(wq, WqHi, WqLo, HID, 4096);
    splitT_kernel<<<dim3(1024 / 32, 4096 / 32), dim3(32, 8)>>>(wk, WkHi, WkLo, HID, 1024);
    splitT_kernel<<<dim3(1024 / 32, 4096 / 32), dim3(32, 8)>>>(wv, WvHi, WvLo, HID, 1024);
    splitT_kernel<<<dim3(4096 / 32, 4096 / 32), dim3(32, 8)>>>(wo, WoHi, WoLo, 4096, HID);

    // Projections
    gemm_mma<1><<<dim3(32, 32), 256, GT_SMEM>>>(Xhi, Xlo, WqHi, WqLo, Qb, M, 4096, HID, NHEADS);
    gemm_mma<1><<<dim3(8, 32), 256, GT_SMEM>>>(Xhi, Xlo, WkHi, WkLo, Kb, M, 1024, HID, NKV);
    gemm_mma<1><<<dim3(8, 32), 256, GT_SMEM>>>(Xhi, Xlo, WvHi, WvLo, Vb, M, 1024, HID, NKV);

    // RoPE + split (Q pre-scaled by SCALING*log2e); plain split for V
    {
        int totq = BATCH * NHEADS * SEQ * 64;
        rope_split<<<(totq + 255) / 256, 256>>>(Qb, cosb, sinb, FQh, FQl, NHEADS, totq, QSCALE);
        int totk = BATCH * NKV * SEQ * 64;
        rope_split<<<(totk + 255) / 256, 256>>>(Kb, cosb, sinb, FKh, FKl, NKV, totk, 1.0f);
        int nkv = BATCH * NKV * SEQ * HD;
        split_kernel<<<(nkv / 4 + 255) / 256, 256>>>(Vb, FVh, FVl, nkv);
    }

    // Flash attention -> attn hi/lo [b,s,h,d]
    flash_mma<<<dim3(NQT, BATCH * NHEADS), 256, FLB_SMEM>>>(
        FQh, FQl, FKh, FKl, FVh, FVl, AtHi, AtLo);

    // Output projection
    gemm_mma<0><<<dim3(32, 32), 256, GT_SMEM>>>(AtHi, AtLo, WoHi, WoLo, out, M, HID, 4096, 0);

    (void)in_sizes; (void)n_in; (void)out_size;
}